// round 12
// baseline (speedup 1.0000x reference)
#include <cuda_runtime.h>
#include <cuda_bf16.h>
#include <math.h>
#include <stdint.h>

// ---- model constants ----
#define Bq   32
#define IMGS 128
#define Dm   512
#define NH   8
#define NL   8
#define MLPD 2048
#define NP   256
#define NT   257
#define HDm  64

// ---- scratch (device globals; no allocation allowed) ----
__device__ float g_comb[Bq * NP * 2 * Dm];           // fp32 for gate-fuse epilogue
__device__ float g_tok [Bq * NT * Dm];
__device__ float g_qkv [Bq * NT * 3 * Dm];
// split-packed bf16 activation operands (hi/lo word arrays)
__device__ uint32_t g_combh[Bq * NP * 512];
__device__ uint32_t g_combl[Bq * NP * 512];
__device__ uint32_t g_xh[Bq * NT * 256];
__device__ uint32_t g_xl[Bq * NT * 256];
__device__ uint32_t g_oh[Bq * NT * 256];
__device__ uint32_t g_ol[Bq * NT * 256];
__device__ uint32_t g_hh[Bq * NT * 1024];
__device__ uint32_t g_hl[Bq * NT * 1024];
// transposed weights, bf16-split, packed: [N][K/2]
#define WT_ELEMS (512*1024 + NL * (1536*512 + 512*512 + 2048*512 + 512*2048))
__device__ uint32_t g_wTh[WT_ELEMS / 2];
__device__ uint32_t g_wTl[WT_ELEMS / 2];

#define FWT_OFFW    0
#define LAYER_OFFW(l) (262144 + (size_t)(l) * 1572864)
#define QKVT_OFFW   0
#define PROJT_OFFW  393216
#define W1T_OFFW    524288
#define W2T_OFFW    1048576

__device__ __forceinline__ void bf16_split_pack(float v0, float v1,
                                                uint32_t& hw, uint32_t& lw) {
    __nv_bfloat16 h0 = __float2bfloat16(v0), h1 = __float2bfloat16(v1);
    float r0 = v0 - __bfloat162float(h0);
    float r1 = v1 - __bfloat162float(h1);
    __nv_bfloat16 l0 = __float2bfloat16(r0), l1 = __float2bfloat16(r1);
    hw = (uint32_t)__bfloat16_as_ushort(h0) | ((uint32_t)__bfloat16_as_ushort(h1) << 16);
    lw = (uint32_t)__bfloat16_as_ushort(l0) | ((uint32_t)__bfloat16_as_ushort(l1) << 16);
}

__device__ __forceinline__ void mma16(float c[4], const uint32_t a[4], const uint32_t b[2]) {
    asm volatile(
        "mma.sync.aligned.m16n8k16.row.col.f32.bf16.bf16.f32 "
        "{%0,%1,%2,%3}, {%4,%5,%6,%7}, {%8,%9}, {%0,%1,%2,%3};"
        : "+f"(c[0]), "+f"(c[1]), "+f"(c[2]), "+f"(c[3])
        : "r"(a[0]), "r"(a[1]), "r"(a[2]), "r"(a[3]), "r"(b[0]), "r"(b[1]));
}

__device__ __forceinline__ void cp16(uint32_t dst, const void* src) {
    asm volatile("cp.async.cg.shared.global [%0], [%1], 16;" :: "r"(dst), "l"(src));
}

// smem: row stride 12 words (8 used + 4 pad -> conflict-free fragment reads)
#define AS_W 12
#define ARR_W 1536              // 128 rows * 12 words per array
#define BUFSTRIDE_W 6144        // 4 arrays per stage
#define NSTAGE 4
#define GEMM_SMEM_BYTES (NSTAGE * BUFSTRIDE_W * 4)   // 96 KB -> 2 CTAs/SM

// ============================================================
// bf16-split GEMM, 4-stage cp.async pipeline, term-major MMA
// ordering (accumulator reuse distance 16). 128x128 tile,
// 256 thr, 8 warps (4M x 2N), warp 32x64.
// act: 0 none, 1 sigmoid, 2 gelu, 3 gate-fuse.
// Requires N%128==0, K%16==0, K/16 >= NSTAGE.
// ============================================================
__global__ __launch_bounds__(256, 2) void mma_gemm(
    const uint32_t* __restrict__ Ah, const uint32_t* __restrict__ Al,
    const uint32_t* __restrict__ BTh, const uint32_t* __restrict__ BTl,
    const float* __restrict__ bias, const float* __restrict__ res,
    float* __restrict__ C, uint32_t* __restrict__ Ch, uint32_t* __restrict__ Cl,
    const float* __restrict__ comb, const float* __restrict__ pos,
    float* __restrict__ tokout,
    int M, int N, int K, int act)
{
    extern __shared__ uint32_t smu[];
    int tid = threadIdx.x;
    int wid = tid >> 5, lane = tid & 31;
    int g = lane >> 2, tig = lane & 3;
    int m0 = blockIdx.y * 128, n0 = blockIdx.x * 128;
    int wmi = wid & 3, wni = wid >> 2;
    int Kw = K >> 1;

    int lr = tid >> 1, lw4 = (tid & 1) * 4;
    int gma = m0 + lr; if (gma > M - 1) gma = M - 1;
    size_t aoff = (size_t)gma * Kw + lw4;
    size_t boff = (size_t)(n0 + lr) * Kw + lw4;
    uint32_t sdb = (uint32_t)__cvta_generic_to_shared(smu) + (uint32_t)(lr * AS_W + lw4) * 4;

    float c[2][8][4] = {};
    int ntiles = K >> 4;

#define ISSUE(T) do {                                                         \
        uint32_t d = sdb + ((T) & (NSTAGE - 1)) * (BUFSTRIDE_W * 4);          \
        size_t ko = (size_t)(T) * 8;                                          \
        cp16(d,                 Ah  + aoff + ko);                             \
        cp16(d + ARR_W * 4,     Al  + aoff + ko);                             \
        cp16(d + ARR_W * 8,     BTh + boff + ko);                             \
        cp16(d + ARR_W * 12,    BTl + boff + ko);                             \
        asm volatile("cp.async.commit_group;" ::: "memory");                  \
    } while (0)

    #pragma unroll
    for (int s = 0; s < NSTAGE - 1; s++) ISSUE(s);

    for (int t = 0; t < ntiles; t++) {
        int rem = ntiles - 1 - t;
        if (rem >= 2)      asm volatile("cp.async.wait_group 2;" ::: "memory");
        else if (rem == 1) asm volatile("cp.async.wait_group 1;" ::: "memory");
        else               asm volatile("cp.async.wait_group 0;" ::: "memory");
        __syncthreads();

        if (t + NSTAGE - 1 < ntiles) ISSUE(t + NSTAGE - 1);

        const uint32_t* bufp = smu + (t & (NSTAGE - 1)) * BUFSTRIDE_W;
        const uint32_t* AhS = bufp;
        const uint32_t* AlS = bufp + ARR_W;
        const uint32_t* BhS = bufp + 2 * ARR_W;
        const uint32_t* BlS = bufp + 3 * ARR_W;

        uint32_t afh[2][4], afl[2][4];
        #pragma unroll
        for (int mf = 0; mf < 2; mf++) {
            int r1 = (wmi * 32 + mf * 16 + g) * AS_W;
            int r2 = r1 + 8 * AS_W;
            afh[mf][0] = AhS[r1 + tig];     afh[mf][1] = AhS[r2 + tig];
            afh[mf][2] = AhS[r1 + tig + 4]; afh[mf][3] = AhS[r2 + tig + 4];
            afl[mf][0] = AlS[r1 + tig];     afl[mf][1] = AlS[r2 + tig];
            afl[mf][2] = AlS[r1 + tig + 4]; afl[mf][3] = AlS[r2 + tig + 4];
        }

        // ---- term-major ordering: each accumulator touched once per pass ----
        // pass 1: afh * B_lo
        #pragma unroll
        for (int nf = 0; nf < 8; nf++) {
            int rb = (wni * 64 + nf * 8 + g) * AS_W;
            uint32_t bl2[2] = {BlS[rb + tig], BlS[rb + tig + 4]};
            mma16(c[0][nf], afh[0], bl2);
            mma16(c[1][nf], afh[1], bl2);
        }
        // pass 2: afl * B_hi
        #pragma unroll
        for (int nf = 0; nf < 8; nf++) {
            int rb = (wni * 64 + nf * 8 + g) * AS_W;
            uint32_t bh2[2] = {BhS[rb + tig], BhS[rb + tig + 4]};
            mma16(c[0][nf], afl[0], bh2);
            mma16(c[1][nf], afl[1], bh2);
        }
        // pass 3: afh * B_hi
        #pragma unroll
        for (int nf = 0; nf < 8; nf++) {
            int rb = (wni * 64 + nf * 8 + g) * AS_W;
            uint32_t bh2[2] = {BhS[rb + tig], BhS[rb + tig + 4]};
            mma16(c[0][nf], afh[0], bh2);
            mma16(c[1][nf], afh[1], bh2);
        }
    }
#undef ISSUE

    // ---- epilogue ----
    int wm = wmi * 32, wn = wni * 64;
    int Nw = N >> 1;
    #pragma unroll
    for (int mf = 0; mf < 2; mf++) {
        #pragma unroll
        for (int rh = 0; rh < 2; rh++) {
            int m = m0 + wm + mf * 16 + g + rh * 8;
            if (m >= M) continue;
            #pragma unroll
            for (int nf = 0; nf < 8; nf++) {
                int n = n0 + wn + nf * 8 + 2 * tig;
                float vx = c[mf][nf][rh * 2], vy = c[mf][nf][rh * 2 + 1];
                if (bias) {
                    float2 bb = *(const float2*)&bias[n];
                    vx += bb.x; vy += bb.y;
                }
                if (act == 1) {
                    vx = 1.f / (1.f + expf(-vx));
                    vy = 1.f / (1.f + expf(-vy));
                } else if (act == 2) {
                    vx = 0.5f * vx * (1.f + erff(vx * 0.70710678118654752f));
                    vy = 0.5f * vy * (1.f + erff(vy * 0.70710678118654752f));
                } else if (act == 3) {
                    float gx = 1.f / (1.f + expf(-vx));
                    float gy = 1.f / (1.f + expf(-vy));
                    size_t mr = (size_t)m * 1024;
                    float2 sv = *(const float2*)&comb[mr + n];
                    float2 ov = *(const float2*)&comb[mr + 512 + n];
                    int p = m & 255, b = m >> 8;
                    float2 pp = *(const float2*)&pos[(size_t)(1 + p) * Dm + n];
                    float ox = gx * sv.x + (1.f - gx) * ov.x + pp.x;
                    float oy = gy * sv.y + (1.f - gy) * ov.y + pp.y;
                    *(float2*)&tokout[((size_t)(b * NT + 1 + p)) * Dm + n] = make_float2(ox, oy);
                    continue;
                }
                if (res) {
                    float2 rr = *(const float2*)&res[(size_t)m * N + n];
                    vx += rr.x; vy += rr.y;
                }
                if (C) *(float2*)&C[(size_t)m * N + n] = make_float2(vx, vy);
                if (Ch) {
                    uint32_t hw_, lw_;
                    bf16_split_pack(vx, vy, hw_, lw_);
                    size_t o = (size_t)m * Nw + (n >> 1);
                    Ch[o] = hw_; Cl[o] = lw_;
                }
            }
        }
    }
}

// ============================================================
// ALL weight transposes in ONE launch
// ============================================================
__global__ void transpose_all(const float* __restrict__ fw,
                              const float* __restrict__ qkvw,
                              const float* __restrict__ projw,
                              const float* __restrict__ w1,
                              const float* __restrict__ w2,
                              uint32_t* __restrict__ dsth,
                              uint32_t* __restrict__ dstl)
{
    int id = blockIdx.x;
    const float* src; int K, N; size_t base; int loc;
    if (id < 512) { src = fw; K = 1024; N = 512; base = 0; loc = id; }
    else {
        int t = id - 512, l = t / 3072, r = t % 3072;
        size_t L = LAYER_OFFW(l);
        if (r < 768)       { src = qkvw  + (size_t)l * 786432;  K = 512;  N = 1536; base = L;               loc = r; }
        else if (r < 1024) { src = projw + (size_t)l * 262144;  K = 512;  N = 512;  base = L + PROJT_OFFW;  loc = r - 768; }
        else if (r < 2048) { src = w1    + (size_t)l * 1048576; K = 512;  N = 2048; base = L + W1T_OFFW;    loc = r - 1024; }
        else               { src = w2    + (size_t)l * 1048576; K = 2048; N = 512;  base = L + W2T_OFFW;    loc = r - 2048; }
    }
    int ntx = N >> 5;
    int kb = (loc / ntx) << 5, nb = (loc % ntx) << 5;

    __shared__ float t[32][33];
    int tx = threadIdx.x & 31, ty = threadIdx.x >> 5;
    #pragma unroll
    for (int j = 0; j < 32; j += 8)
        t[ty + j][tx] = src[(size_t)(kb + ty + j) * N + nb + tx];
    __syncthreads();

    int w = threadIdx.x & 15, r2 = threadIdx.x >> 4;
    int Kw = K >> 1;
    #pragma unroll
    for (int j = 0; j < 32; j += 16) {
        int row = r2 + j;
        float v0 = t[2 * w][row], v1 = t[2 * w + 1][row];
        uint32_t hw_, lw_; bf16_split_pack(v0, v1, hw_, lw_);
        size_t o = base + (size_t)(nb + row) * Kw + (kb >> 1) + w;
        dsth[o] = hw_; dstl[o] = lw_;
    }
}

// ============================================================
// SPT: conv + LN, writes fp32 comb AND split-packed comb
// ============================================================
__device__ __forceinline__ float ln512(float a, float* red, int tid) {
    red[tid] = a; __syncthreads();
    for (int s = 256; s > 0; s >>= 1) { if (tid < s) red[tid] += red[tid + s]; __syncthreads(); }
    float mu = red[0] * (1.f / 512.f); __syncthreads();
    float dv = a - mu;
    red[tid] = dv * dv; __syncthreads();
    for (int s = 256; s > 0; s >>= 1) { if (tid < s) red[tid] += red[tid + s]; __syncthreads(); }
    float var = red[0] * (1.f / 512.f); __syncthreads();
    return dv * rsqrtf(var + 1e-5f);
}

__global__ void spt_kernel(const float* __restrict__ img,
    const float* __restrict__ w0, const float* __restrict__ bb0,
    const float* __restrict__ gg0, const float* __restrict__ be0,
    const float* __restrict__ w1, const float* __restrict__ bb1,
    const float* __restrict__ gg1, const float* __restrict__ be1,
    float* __restrict__ comb, uint32_t* __restrict__ combh, uint32_t* __restrict__ combl)
{
    int blk = blockIdx.x;
    int b = blk >> 8;
    int p = blk & 255;
    int py = p >> 4, px = p & 15;

    __shared__ float patch[10][10];
    __shared__ float red[512];
    int tid = threadIdx.x;

    if (tid < 100) {
        int r = tid / 10, c = tid % 10;
        int ir = (py * 8 - 1 + r) & 127;
        int ic = (px * 8 - 1 + c) & 127;
        patch[r][c] = img[((size_t)b * IMGS + ir) * IMGS + ic];
    }
    __syncthreads();

    const int dy[5] = {1, 0, 2, 0, 2};
    const int dx[5] = {1, 0, 0, 2, 2};

    int d = tid;
    float a0 = bb0[d], a1 = bb1[d];
    const float* wp0 = w0 + (size_t)d * 320;
    const float* wp1 = w1 + (size_t)d * 320;

    for (int c = 0; c < 5; c++) {
        #pragma unroll
        for (int i = 0; i < 8; i++) {
            #pragma unroll
            for (int j = 0; j < 8; j++) {
                float xv = patch[i + dy[c]][j + dx[c]];
                int wi = (c * 8 + i) * 8 + j;
                a0 = fmaf(wp0[wi], xv, a0);
                a1 = fmaf(wp1[wi], xv, a1);
            }
        }
    }

    float n0 = ln512(a0, red, tid) * gg0[d] + be0[d];
    float n1 = ln512(a1, red, tid) * gg1[d] + be1[d];

    size_t row = blk;
    comb[row * 1024 + d]       = n0;
    comb[row * 1024 + 512 + d] = n1;

    red[tid] = n0; __syncthreads();
    if (tid < 256) {
        uint32_t h, l; bf16_split_pack(red[2 * tid], red[2 * tid + 1], h, l);
        combh[row * 512 + tid] = h; combl[row * 512 + tid] = l;
    }
    __syncthreads();
    red[tid] = n1; __syncthreads();
    if (tid < 256) {
        uint32_t h, l; bf16_split_pack(red[2 * tid], red[2 * tid + 1], h, l);
        combh[row * 512 + 256 + tid] = h; combl[row * 512 + 256 + tid] = l;
    }
}

// ============================================================
// LayerNorm over D=512 -> split-packed output
// ============================================================
__global__ void ln_kernel(const float* __restrict__ in, const float* __restrict__ g,
                          const float* __restrict__ bta,
                          uint32_t* __restrict__ xh, uint32_t* __restrict__ xl)
{
    int row = blockIdx.x, tid = threadIdx.x;   // 128
    __shared__ float red[128];
    float4 v = *(const float4*)&in[(size_t)row * Dm + tid * 4];
    red[tid] = v.x + v.y + v.z + v.w; __syncthreads();
    for (int st = 64; st > 0; st >>= 1) { if (tid < st) red[tid] += red[tid + st]; __syncthreads(); }
    float mu = red[0] * (1.f / 512.f); __syncthreads();
    float dx = v.x - mu, dyv = v.y - mu, dz = v.z - mu, dw = v.w - mu;
    red[tid] = dx * dx + dyv * dyv + dz * dz + dw * dw; __syncthreads();
    for (int st = 64; st > 0; st >>= 1) { if (tid < st) red[tid] += red[tid + st]; __syncthreads(); }
    float inv = rsqrtf(red[0] * (1.f / 512.f) + 1e-5f);
    float4 gg = *(const float4*)&g[tid * 4];
    float4 bb = *(const float4*)&bta[tid * 4];
    float y0 = dx  * inv * gg.x + bb.x;
    float y1 = dyv * inv * gg.y + bb.y;
    float y2 = dz  * inv * gg.z + bb.z;
    float y3 = dw  * inv * gg.w + bb.w;
    uint32_t h0, l0, h1, l1;
    bf16_split_pack(y0, y1, h0, l0);
    bf16_split_pack(y2, y3, h1, l1);
    size_t o = (size_t)row * 256 + tid * 2;
    xh[o] = h0; xh[o + 1] = h1;
    xl[o] = l0; xl[o + 1] = l1;
}

// ============================================================
// Tiled fused attention -> split-packed o
// ============================================================
#define QTILES 5
#define SS_LD  260
#define ATTN_SMEM ((64*68 + 64*68 + 64*SS_LD) * 4)

__global__ __launch_bounds__(256) void attn_kernel(
    const float* __restrict__ qkv, const float* __restrict__ temp,
    uint32_t* __restrict__ oh, uint32_t* __restrict__ ol)
{
    extern __shared__ float smf[];
    float* Qs  = smf;
    float* KVs = smf + 64 * 68;
    float* Ss  = smf + 2 * 64 * 68;

    int qt = blockIdx.x, h = blockIdx.y, b = blockIdx.z;
    int tid = threadIdx.x;
    int tx = tid & 15, ty = tid >> 4;

    const size_t base = (size_t)b * NT * 1536 + (size_t)h * 64;

    {
        int dth = (tid & 15) * 4;
        #pragma unroll
        for (int pass = 0; pass < 4; pass++) {
            int q = (tid >> 4) + pass * 16;
            int n = qt * 64 + q; if (n > NT - 1) n = NT - 1;
            float4 v = *(const float4*)&qkv[base + (size_t)n * 1536 + dth];
            Qs[(dth + 0) * 68 + q] = v.x;
            Qs[(dth + 1) * 68 + q] = v.y;
            Qs[(dth + 2) * 68 + q] = v.z;
            Qs[(dth + 3) * 68 + q] = v.w;
        }
    }

    float tmp = temp[h];
    int nbase = qt * 64;

    for (int mc = 0; mc < NT; mc += 64) {
        __syncthreads();
        {
            int dth = (tid & 15) * 4;
            #pragma unroll
            for (int pass = 0; pass < 4; pass++) {
                int m = (tid >> 4) + pass * 16;
                int mg = mc + m; if (mg > NT - 1) mg = NT - 1;
                float4 v = *(const float4*)&qkv[base + 512 + (size_t)mg * 1536 + dth];
                KVs[(dth + 0) * 68 + m] = v.x;
                KVs[(dth + 1) * 68 + m] = v.y;
                KVs[(dth + 2) * 68 + m] = v.z;
                KVs[(dth + 3) * 68 + m] = v.w;
            }
        }
        __syncthreads();

        float acc[4][4] = {};
        #pragma unroll
        for (int kk = 0; kk < 64; kk++) {
            float4 a = *(const float4*)&Qs[kk * 68 + ty * 4];
            float4 bb = *(const float4*)&KVs[kk * 68 + tx * 4];
            float av[4] = {a.x, a.y, a.z, a.w};
            float bv[4] = {bb.x, bb.y, bb.z, bb.w};
            #pragma unroll
            for (int i = 0; i < 4; i++)
                #pragma unroll
                for (int j = 0; j < 4; j++)
                    acc[i][j] = fmaf(av[i], bv[j], acc[i][j]);
        }
        #pragma unroll
        for (int i = 0; i < 4; i++) {
            int q = ty * 4 + i;
            int n = nbase + q;
            #pragma unroll
            for (int j = 0; j < 4; j++) {
                int m = mc + tx * 4 + j;
                if (m < NT) {
                    float s = acc[i][j] * tmp;
                    if (m == n) s = -INFINITY;
                    Ss[q * SS_LD + m] = s;
                }
            }
        }
    }
    __syncthreads();

    {
        int wid = tid >> 5, lane = tid & 31;
        for (int r = 0; r < 8; r++) {
            float* row = Ss + (wid * 8 + r) * SS_LD;
            float mx = -INFINITY;
            for (int m = lane; m < NT; m += 32) mx = fmaxf(mx, row[m]);
            #pragma unroll
            for (int s = 16; s > 0; s >>= 1) mx = fmaxf(mx, __shfl_xor_sync(0xffffffffu, mx, s));
            float sum = 0.f;
            for (int m = lane; m < NT; m += 32) { float e = expf(row[m] - mx); row[m] = e; sum += e; }
            #pragma unroll
            for (int s = 16; s > 0; s >>= 1) sum += __shfl_xor_sync(0xffffffffu, sum, s);
            float inv = 1.f / sum;
            for (int m = lane; m < NT; m += 32) row[m] *= inv;
        }
    }

    float acc[4][4] = {};
    for (int mc = 0; mc < NT; mc += 64) {
        __syncthreads();
        {
            int dth = (tid & 15) * 4;
            #pragma unroll
            for (int pass = 0; pass < 4; pass++) {
                int m = (tid >> 4) + pass * 16;
                int mg = mc + m; if (mg > NT - 1) mg = NT - 1;
                float4 v = *(const float4*)&qkv[base + 1024 + (size_t)mg * 1536 + dth];
                *(float4*)&KVs[m * 68 + dth] = v;
            }
        }
        __syncthreads();
        int mlim = NT - mc; if (mlim > 64) mlim = 64;
        for (int mm = 0; mm < mlim; mm++) {
            float4 bb = *(const float4*)&KVs[mm * 68 + tx * 4];
            float bv[4] = {bb.x, bb.y, bb.z, bb.w};
            #pragma unroll
            for (int i = 0; i < 4; i++) {
                float p = Ss[(ty * 4 + i) * SS_LD + mc + mm];
                #pragma unroll
                for (int j = 0; j < 4; j++)
                    acc[i][j] = fmaf(p, bv[j], acc[i][j]);
            }
        }
    }

    #pragma unroll
    for (int i = 0; i < 4; i++) {
        int n = nbase + ty * 4 + i;
        if (n < NT) {
            uint32_t h0, l0, h1, l1;
            bf16_split_pack(acc[i][0], acc[i][1], h0, l0);
            bf16_split_pack(acc[i][2], acc[i][3], h1, l1);
            size_t o = (size_t)(b * NT + n) * 256 + h * 32 + tx * 2;
            oh[o] = h0; oh[o + 1] = h1;
            ol[o] = l0; ol[o + 1] = l1;
        }
    }
}

// ============================================================
// cls row init
// ============================================================
__global__ void cls_kernel(const float* __restrict__ cls, const float* __restrict__ pos,
                           float* __restrict__ tok)
{
    int idx = blockIdx.x * blockDim.x + threadIdx.x;
    if (idx >= Bq * Dm) return;
    int d = idx & 511, b = idx >> 9;
    tok[(size_t)b * NT * Dm + d] = cls[d] + pos[d];
}

// ============================================================
// Head
// ============================================================
__global__ void head_kernel(const float* __restrict__ tok, const float* __restrict__ ng,
                            const float* __restrict__ nb, const float* __restrict__ hw,
                            const float* __restrict__ hb, float* __restrict__ out)
{
    int b = blockIdx.x, tid = threadIdx.x;
    __shared__ float red[128];
    const float* xr = tok + (size_t)b * NT * Dm;
    float v[4]; float s = 0.f;
    #pragma unroll
    for (int i = 0; i < 4; i++) { v[i] = xr[tid + 128 * i]; s += v[i]; }
    red[tid] = s; __syncthreads();
    for (int st = 64; st > 0; st >>= 1) { if (tid < st) red[tid] += red[tid + st]; __syncthreads(); }
    float mu = red[0] * (1.f / 512.f); __syncthreads();
    float s2 = 0.f;
    #pragma unroll
    for (int i = 0; i < 4; i++) { float dv = v[i] - mu; s2 += dv * dv; }
    red[tid] = s2; __syncthreads();
    for (int st = 64; st > 0; st >>= 1) { if (tid < st) red[tid] += red[tid + st]; __syncthreads(); }
    float inv = rsqrtf(red[0] * (1.f / 512.f) + 1e-5f);
    __syncthreads();

    float xn[4];
    #pragma unroll
    for (int i = 0; i < 4; i++) {
        int idx = tid + 128 * i;
        xn[i] = (v[i] - mu) * inv * ng[idx] + nb[idx];
    }

    for (int c = 0; c < 3; c++) {
        float p = 0.f;
        #pragma unroll
        for (int i = 0; i < 4; i++) {
            int idx = tid + 128 * i;
            p = fmaf(xn[i], hw[idx * 3 + c], p);
        }
        red[tid] = p; __syncthreads();
        for (int st = 64; st > 0; st >>= 1) { if (tid < st) red[tid] += red[tid + st]; __syncthreads(); }
        if (tid == 0) out[b * 3 + c] = red[0] + hb[c];
        __syncthreads();
    }
}

// ============================================================
// Launch
// ============================================================
static uint32_t* s_wTh = nullptr;
static uint32_t* s_wTl = nullptr;

static inline void launch_gemm(const uint32_t* Ah, const uint32_t* Al, size_t wOffW,
                               const float* bias, const float* res,
                               float* C, uint32_t* Ch, uint32_t* Cl,
                               const float* comb, const float* pos, float* tokout,
                               int M, int Nn, int K, int act)
{
    dim3 grid(Nn / 128, (M + 127) / 128);
    mma_gemm<<<grid, 256, GEMM_SMEM_BYTES>>>(Ah, Al, s_wTh + wOffW, s_wTl + wOffW,
                                             bias, res, C, Ch, Cl, comb, pos, tokout,
                                             M, Nn, K, act);
}

extern "C" void kernel_launch(void* const* d_in, const int* in_sizes, int n_in,
                              void* d_out, int out_size)
{
    const float* image   = (const float*)d_in[0];
    const float* ssw     = (const float*)d_in[1];
    const float* ssb     = (const float*)d_in[2];
    const float* ssg     = (const float*)d_in[3];
    const float* ssbeta  = (const float*)d_in[4];
    const float* sow     = (const float*)d_in[5];
    const float* sob     = (const float*)d_in[6];
    const float* sog     = (const float*)d_in[7];
    const float* sobeta  = (const float*)d_in[8];
    const float* fw      = (const float*)d_in[9];
    const float* fb      = (const float*)d_in[10];
    const float* cls     = (const float*)d_in[11];
    const float* pos     = (const float*)d_in[12];
    const float* ln1g    = (const float*)d_in[13];
    const float* ln1b    = (const float*)d_in[14];
    const float* qkvw    = (const float*)d_in[15];
    const float* qkvb    = (const float*)d_in[16];
    const float* projw   = (const float*)d_in[17];
    const float* projb   = (const float*)d_in[18];
    const float* temp    = (const float*)d_in[19];
    const float* ln2g    = (const float*)d_in[20];
    const float* ln2b    = (const float*)d_in[21];
    const float* w1      = (const float*)d_in[22];
    const float* b1      = (const float*)d_in[23];
    const float* w2      = (const float*)d_in[24];
    const float* b2      = (const float*)d_in[25];
    const float* ng      = (const float*)d_in[26];
    const float* nb      = (const float*)d_in[27];
    const float* hw      = (const float*)d_in[28];
    const float* hb      = (const float*)d_in[29];

    float *comb, *tok, *qkv;
    uint32_t *combh, *combl, *xh, *xl, *oh, *ol, *hh, *hl;
    cudaGetSymbolAddress((void**)&comb,  g_comb);
    cudaGetSymbolAddress((void**)&tok,   g_tok);
    cudaGetSymbolAddress((void**)&qkv,   g_qkv);
    cudaGetSymbolAddress((void**)&combh, g_combh);
    cudaGetSymbolAddress((void**)&combl, g_combl);
    cudaGetSymbolAddress((void**)&xh,    g_xh);
    cudaGetSymbolAddress((void**)&xl,    g_xl);
    cudaGetSymbolAddress((void**)&oh,    g_oh);
    cudaGetSymbolAddress((void**)&ol,    g_ol);
    cudaGetSymbolAddress((void**)&hh,    g_hh);
    cudaGetSymbolAddress((void**)&hl,    g_hl);
    cudaGetSymbolAddress((void**)&s_wTh, g_wTh);
    cudaGetSymbolAddress((void**)&s_wTl, g_wTl);

    cudaFuncSetAttribute(mma_gemm, cudaFuncAttributeMaxDynamicSharedMemorySize, GEMM_SMEM_BYTES);
    cudaFuncSetAttribute(attn_kernel, cudaFuncAttributeMaxDynamicSharedMemorySize, ATTN_SMEM);

    const int Mtok = Bq * NT;   // 8224
    const int Mpat = Bq * NP;   // 8192

    // launch 0: cls init (tiny)
    cls_kernel<<<(Bq * Dm + 255) / 256, 256>>>(cls, pos, tok);
    // launch 1: weight transposes
    transpose_all<<<25088, 256>>>(fw, qkvw, projw, w1, w2, s_wTh, s_wTl);
    // launch 2: SPT
    spt_kernel<<<Mpat, 512>>>(image, ssw, ssb, ssg, ssbeta,
                              sow, sob, sog, sobeta, comb, combh, combl);
    // launch 3: gate GEMM with fused token-mix epilogue  <-- profiled slot
    launch_gemm(combh, combl, FWT_OFFW, fb, nullptr, nullptr, nullptr, nullptr,
                comb, pos, tok, Mpat, Dm, 2 * Dm, /*gate-fuse*/3);

    for (int l = 0; l < NL; l++) {
        size_t lb = LAYER_OFFW(l);
        ln_kernel<<<Mtok, 128>>>(tok, ln1g + l * Dm, ln1b + l * Dm, xh, xl);
        launch_gemm(xh, xl, lb + QKVT_OFFW, qkvb + l * 3 * Dm, nullptr,
                    qkv, nullptr, nullptr, nullptr, nullptr, nullptr, Mtok, 3 * Dm, Dm, 0);
        attn_kernel<<<dim3(QTILES, NH, Bq), 256, ATTN_SMEM>>>(qkv, temp + l * NH, oh, ol);
        launch_gemm(oh, ol, lb + PROJT_OFFW, projb + l * Dm, tok,
                    tok, nullptr, nullptr, nullptr, nullptr, nullptr, Mtok, Dm, Dm, 0);
        ln_kernel<<<Mtok, 128>>>(tok, ln2g + l * Dm, ln2b + l * Dm, xh, xl);
        launch_gemm(xh, xl, lb + W1T_OFFW, b1 + l * MLPD, nullptr,
                    nullptr, hh, hl, nullptr, nullptr, nullptr, Mtok, MLPD, Dm, /*gelu*/2);
        launch_gemm(hh, hl, lb + W2T_OFFW, b2 + l * Dm, tok,
                    tok, nullptr, nullptr, nullptr, nullptr, nullptr, Mtok, Dm, MLPD, 0);
    }

    head_kernel<<<Bq, 128>>>(tok, ng, nb, hw, hb, (float*)d_out);
}

// round 13
// speedup vs baseline: 1.0768x; 1.0768x over previous
#include <cuda_runtime.h>
#include <cuda_bf16.h>
#include <math.h>
#include <stdint.h>

// ---- model constants ----
#define Bq   32
#define IMGS 128
#define Dm   512
#define NH   8
#define NL   8
#define MLPD 2048
#define NP   256
#define NT   257
#define HDm  64

// ---- scratch (device globals; no allocation allowed) ----
__device__ float g_comb[Bq * NP * 2 * Dm];
__device__ float g_tok [Bq * NT * Dm];
// split-packed bf16 activation operands (hi/lo word arrays)
__device__ uint32_t g_combh[Bq * NP * 512];
__device__ uint32_t g_combl[Bq * NP * 512];
__device__ uint32_t g_xh[Bq * NT * 256];
__device__ uint32_t g_xl[Bq * NT * 256];
__device__ uint32_t g_qkvh[Bq * NT * 768];
__device__ uint32_t g_qkvl[Bq * NT * 768];
__device__ uint32_t g_oh[Bq * NT * 256];
__device__ uint32_t g_ol[Bq * NT * 256];
__device__ uint32_t g_hh[Bq * NT * 1024];
__device__ uint32_t g_hl[Bq * NT * 1024];
// transposed weights, bf16-split, packed: [N][K/2]
#define WT_ELEMS (512*1024 + NL * (1536*512 + 512*512 + 2048*512 + 512*2048))
__device__ uint32_t g_wTh[WT_ELEMS / 2];
__device__ uint32_t g_wTl[WT_ELEMS / 2];

#define FWT_OFFW    0
#define LAYER_OFFW(l) (262144 + (size_t)(l) * 1572864)
#define QKVT_OFFW   0
#define PROJT_OFFW  393216
#define W1T_OFFW    524288
#define W2T_OFFW    1048576

__device__ __forceinline__ void bf16_split_pack(float v0, float v1,
                                                uint32_t& hw, uint32_t& lw) {
    __nv_bfloat16 h0 = __float2bfloat16(v0), h1 = __float2bfloat16(v1);
    float r0 = v0 - __bfloat162float(h0);
    float r1 = v1 - __bfloat162float(h1);
    __nv_bfloat16 l0 = __float2bfloat16(r0), l1 = __float2bfloat16(r1);
    hw = (uint32_t)__bfloat16_as_ushort(h0) | ((uint32_t)__bfloat16_as_ushort(h1) << 16);
    lw = (uint32_t)__bfloat16_as_ushort(l0) | ((uint32_t)__bfloat16_as_ushort(l1) << 16);
}
__device__ __forceinline__ float bf_lo(uint32_t w) {
    return __bfloat162float(__ushort_as_bfloat16((unsigned short)(w & 0xffff)));
}
__device__ __forceinline__ float bf_hi(uint32_t w) {
    return __bfloat162float(__ushort_as_bfloat16((unsigned short)(w >> 16)));
}

__device__ __forceinline__ void mma16(float c[4], const uint32_t a[4], const uint32_t b[2]) {
    asm volatile(
        "mma.sync.aligned.m16n8k16.row.col.f32.bf16.bf16.f32 "
        "{%0,%1,%2,%3}, {%4,%5,%6,%7}, {%8,%9}, {%0,%1,%2,%3};"
        : "+f"(c[0]), "+f"(c[1]), "+f"(c[2]), "+f"(c[3])
        : "r"(a[0]), "r"(a[1]), "r"(a[2]), "r"(a[3]), "r"(b[0]), "r"(b[1]));
}

__device__ __forceinline__ void cp16(uint32_t dst, const void* src) {
    asm volatile("cp.async.cg.shared.global [%0], [%1], 16;" :: "r"(dst), "l"(src));
}

// ================= GEMM (R10 config, proven) =================
#define AS_W 12
#define ARR_W 1536
#define BUFSTRIDE_W 6144
#define NSTAGE 4
#define GEMM_SMEM_BYTES (NSTAGE * BUFSTRIDE_W * 4)

__global__ __launch_bounds__(256, 2) void mma_gemm(
    const uint32_t* __restrict__ Ah, const uint32_t* __restrict__ Al,
    const uint32_t* __restrict__ BTh, const uint32_t* __restrict__ BTl,
    const float* __restrict__ bias, const float* __restrict__ res,
    float* __restrict__ C, uint32_t* __restrict__ Ch, uint32_t* __restrict__ Cl,
    const float* __restrict__ comb, const float* __restrict__ pos,
    float* __restrict__ tokout,
    int M, int N, int K, int act)
{
    extern __shared__ uint32_t smu[];
    int tid = threadIdx.x;
    int wid = tid >> 5, lane = tid & 31;
    int g = lane >> 2, tig = lane & 3;
    int m0 = blockIdx.y * 128, n0 = blockIdx.x * 128;
    int wmi = wid & 3, wni = wid >> 2;
    int Kw = K >> 1;

    int lr = tid >> 1, lw4 = (tid & 1) * 4;
    int gma = m0 + lr; if (gma > M - 1) gma = M - 1;
    size_t aoff = (size_t)gma * Kw + lw4;
    size_t boff = (size_t)(n0 + lr) * Kw + lw4;
    uint32_t sdb = (uint32_t)__cvta_generic_to_shared(smu) + (uint32_t)(lr * AS_W + lw4) * 4;

    float c[2][8][4] = {};
    int ntiles = K >> 4;

#define ISSUE(T) do {                                                         \
        uint32_t d = sdb + ((T) & (NSTAGE - 1)) * (BUFSTRIDE_W * 4);          \
        size_t ko = (size_t)(T) * 8;                                          \
        cp16(d,                 Ah  + aoff + ko);                             \
        cp16(d + ARR_W * 4,     Al  + aoff + ko);                             \
        cp16(d + ARR_W * 8,     BTh + boff + ko);                             \
        cp16(d + ARR_W * 12,    BTl + boff + ko);                             \
        asm volatile("cp.async.commit_group;" ::: "memory");                  \
    } while (0)

    #pragma unroll
    for (int s = 0; s < NSTAGE - 1; s++) ISSUE(s);

    for (int t = 0; t < ntiles; t++) {
        int rem = ntiles - 1 - t;
        if (rem >= 2)      asm volatile("cp.async.wait_group 2;" ::: "memory");
        else if (rem == 1) asm volatile("cp.async.wait_group 1;" ::: "memory");
        else               asm volatile("cp.async.wait_group 0;" ::: "memory");
        __syncthreads();

        if (t + NSTAGE - 1 < ntiles) ISSUE(t + NSTAGE - 1);

        const uint32_t* bufp = smu + (t & (NSTAGE - 1)) * BUFSTRIDE_W;
        const uint32_t* AhS = bufp;
        const uint32_t* AlS = bufp + ARR_W;
        const uint32_t* BhS = bufp + 2 * ARR_W;
        const uint32_t* BlS = bufp + 3 * ARR_W;

        uint32_t afh[2][4], afl[2][4];
        #pragma unroll
        for (int mf = 0; mf < 2; mf++) {
            int r1 = (wmi * 32 + mf * 16 + g) * AS_W;
            int r2 = r1 + 8 * AS_W;
            afh[mf][0] = AhS[r1 + tig];     afh[mf][1] = AhS[r2 + tig];
            afh[mf][2] = AhS[r1 + tig + 4]; afh[mf][3] = AhS[r2 + tig + 4];
            afl[mf][0] = AlS[r1 + tig];     afl[mf][1] = AlS[r2 + tig];
            afl[mf][2] = AlS[r1 + tig + 4]; afl[mf][3] = AlS[r2 + tig + 4];
        }
        #pragma unroll
        for (int nf = 0; nf < 8; nf++) {
            int rb = (wni * 64 + nf * 8 + g) * AS_W;
            uint32_t bh2[2] = {BhS[rb + tig], BhS[rb + tig + 4]};
            uint32_t bl2[2] = {BlS[rb + tig], BlS[rb + tig + 4]};
            #pragma unroll
            for (int mf = 0; mf < 2; mf++) {
                mma16(c[mf][nf], afh[mf], bl2);
                mma16(c[mf][nf], afl[mf], bh2);
                mma16(c[mf][nf], afh[mf], bh2);
            }
        }
    }
#undef ISSUE

    int wm = wmi * 32, wn = wni * 64;
    int Nw = N >> 1;
    #pragma unroll
    for (int mf = 0; mf < 2; mf++) {
        #pragma unroll
        for (int rh = 0; rh < 2; rh++) {
            int m = m0 + wm + mf * 16 + g + rh * 8;
            if (m >= M) continue;
            #pragma unroll
            for (int nf = 0; nf < 8; nf++) {
                int n = n0 + wn + nf * 8 + 2 * tig;
                float vx = c[mf][nf][rh * 2], vy = c[mf][nf][rh * 2 + 1];
                if (bias) {
                    float2 bb = *(const float2*)&bias[n];
                    vx += bb.x; vy += bb.y;
                }
                if (act == 1) {
                    vx = 1.f / (1.f + expf(-vx));
                    vy = 1.f / (1.f + expf(-vy));
                } else if (act == 2) {
                    vx = 0.5f * vx * (1.f + erff(vx * 0.70710678118654752f));
                    vy = 0.5f * vy * (1.f + erff(vy * 0.70710678118654752f));
                } else if (act == 3) {
                    float gx = 1.f / (1.f + expf(-vx));
                    float gy = 1.f / (1.f + expf(-vy));
                    size_t mr = (size_t)m * 1024;
                    float2 sv = *(const float2*)&comb[mr + n];
                    float2 ov = *(const float2*)&comb[mr + 512 + n];
                    int p = m & 255, b = m >> 8;
                    float2 pp = *(const float2*)&pos[(size_t)(1 + p) * Dm + n];
                    float ox = gx * sv.x + (1.f - gx) * ov.x + pp.x;
                    float oy = gy * sv.y + (1.f - gy) * ov.y + pp.y;
                    *(float2*)&tokout[((size_t)(b * NT + 1 + p)) * Dm + n] = make_float2(ox, oy);
                    continue;
                }
                if (res) {
                    float2 rr = *(const float2*)&res[(size_t)m * N + n];
                    vx += rr.x; vy += rr.y;
                }
                if (C) *(float2*)&C[(size_t)m * N + n] = make_float2(vx, vy);
                if (Ch) {
                    uint32_t hw_, lw_;
                    bf16_split_pack(vx, vy, hw_, lw_);
                    size_t o = (size_t)m * Nw + (n >> 1);
                    Ch[o] = hw_; Cl[o] = lw_;
                }
            }
        }
    }
}

// ============================================================
// ALL weight transposes in ONE launch
// ============================================================
__global__ void transpose_all(const float* __restrict__ fw,
                              const float* __restrict__ qkvw,
                              const float* __restrict__ projw,
                              const float* __restrict__ w1,
                              const float* __restrict__ w2,
                              uint32_t* __restrict__ dsth,
                              uint32_t* __restrict__ dstl)
{
    int id = blockIdx.x;
    const float* src; int K, N; size_t base; int loc;
    if (id < 512) { src = fw; K = 1024; N = 512; base = 0; loc = id; }
    else {
        int t = id - 512, l = t / 3072, r = t % 3072;
        size_t L = LAYER_OFFW(l);
        if (r < 768)       { src = qkvw  + (size_t)l * 786432;  K = 512;  N = 1536; base = L;               loc = r; }
        else if (r < 1024) { src = projw + (size_t)l * 262144;  K = 512;  N = 512;  base = L + PROJT_OFFW;  loc = r - 768; }
        else if (r < 2048) { src = w1    + (size_t)l * 1048576; K = 512;  N = 2048; base = L + W1T_OFFW;    loc = r - 1024; }
        else               { src = w2    + (size_t)l * 1048576; K = 2048; N = 512;  base = L + W2T_OFFW;    loc = r - 2048; }
    }
    int ntx = N >> 5;
    int kb = (loc / ntx) << 5, nb = (loc % ntx) << 5;

    __shared__ float t[32][33];
    int tx = threadIdx.x & 31, ty = threadIdx.x >> 5;
    #pragma unroll
    for (int j = 0; j < 32; j += 8)
        t[ty + j][tx] = src[(size_t)(kb + ty + j) * N + nb + tx];
    __syncthreads();

    int w = threadIdx.x & 15, r2 = threadIdx.x >> 4;
    int Kw = K >> 1;
    #pragma unroll
    for (int j = 0; j < 32; j += 16) {
        int row = r2 + j;
        float v0 = t[2 * w][row], v1 = t[2 * w + 1][row];
        uint32_t hw_, lw_; bf16_split_pack(v0, v1, hw_, lw_);
        size_t o = base + (size_t)(nb + row) * Kw + (kb >> 1) + w;
        dsth[o] = hw_; dstl[o] = lw_;
    }
}

// ============================================================
// SPT: conv + LN, writes fp32 comb AND split-packed comb
// ============================================================
__device__ __forceinline__ float ln512(float a, float* red, int tid) {
    red[tid] = a; __syncthreads();
    for (int s = 256; s > 0; s >>= 1) { if (tid < s) red[tid] += red[tid + s]; __syncthreads(); }
    float mu = red[0] * (1.f / 512.f); __syncthreads();
    float dv = a - mu;
    red[tid] = dv * dv; __syncthreads();
    for (int s = 256; s > 0; s >>= 1) { if (tid < s) red[tid] += red[tid + s]; __syncthreads(); }
    float var = red[0] * (1.f / 512.f); __syncthreads();
    return dv * rsqrtf(var + 1e-5f);
}

__global__ void spt_kernel(const float* __restrict__ img,
    const float* __restrict__ w0, const float* __restrict__ bb0,
    const float* __restrict__ gg0, const float* __restrict__ be0,
    const float* __restrict__ w1, const float* __restrict__ bb1,
    const float* __restrict__ gg1, const float* __restrict__ be1,
    float* __restrict__ comb, uint32_t* __restrict__ combh, uint32_t* __restrict__ combl)
{
    int blk = blockIdx.x;
    int b = blk >> 8;
    int p = blk & 255;
    int py = p >> 4, px = p & 15;

    __shared__ float patch[10][10];
    __shared__ float red[512];
    int tid = threadIdx.x;

    if (tid < 100) {
        int r = tid / 10, c = tid % 10;
        int ir = (py * 8 - 1 + r) & 127;
        int ic = (px * 8 - 1 + c) & 127;
        patch[r][c] = img[((size_t)b * IMGS + ir) * IMGS + ic];
    }
    __syncthreads();

    const int dy[5] = {1, 0, 2, 0, 2};
    const int dx[5] = {1, 0, 0, 2, 2};

    int d = tid;
    float a0 = bb0[d], a1 = bb1[d];
    const float* wp0 = w0 + (size_t)d * 320;
    const float* wp1 = w1 + (size_t)d * 320;

    for (int c = 0; c < 5; c++) {
        #pragma unroll
        for (int i = 0; i < 8; i++) {
            #pragma unroll
            for (int j = 0; j < 8; j++) {
                float xv = patch[i + dy[c]][j + dx[c]];
                int wi = (c * 8 + i) * 8 + j;
                a0 = fmaf(wp0[wi], xv, a0);
                a1 = fmaf(wp1[wi], xv, a1);
            }
        }
    }

    float n0 = ln512(a0, red, tid) * gg0[d] + be0[d];
    float n1 = ln512(a1, red, tid) * gg1[d] + be1[d];

    size_t row = blk;
    comb[row * 1024 + d]       = n0;
    comb[row * 1024 + 512 + d] = n1;

    red[tid] = n0; __syncthreads();
    if (tid < 256) {
        uint32_t h, l; bf16_split_pack(red[2 * tid], red[2 * tid + 1], h, l);
        combh[row * 512 + tid] = h; combl[row * 512 + tid] = l;
    }
    __syncthreads();
    red[tid] = n1; __syncthreads();
    if (tid < 256) {
        uint32_t h, l; bf16_split_pack(red[2 * tid], red[2 * tid + 1], h, l);
        combh[row * 512 + 256 + tid] = h; combl[row * 512 + 256 + tid] = l;
    }
}

// ============================================================
// LayerNorm over D=512 -> split-packed output
// ============================================================
__global__ void ln_kernel(const float* __restrict__ in, const float* __restrict__ g,
                          const float* __restrict__ bta,
                          uint32_t* __restrict__ xh, uint32_t* __restrict__ xl)
{
    int row = blockIdx.x, tid = threadIdx.x;   // 128
    __shared__ float red[128];
    float4 v = *(const float4*)&in[(size_t)row * Dm + tid * 4];
    red[tid] = v.x + v.y + v.z + v.w; __syncthreads();
    for (int st = 64; st > 0; st >>= 1) { if (tid < st) red[tid] += red[tid + st]; __syncthreads(); }
    float mu = red[0] * (1.f / 512.f); __syncthreads();
    float dx = v.x - mu, dyv = v.y - mu, dz = v.z - mu, dw = v.w - mu;
    red[tid] = dx * dx + dyv * dyv + dz * dz + dw * dw; __syncthreads();
    for (int st = 64; st > 0; st >>= 1) { if (tid < st) red[tid] += red[tid + st]; __syncthreads(); }
    float inv = rsqrtf(red[0] * (1.f / 512.f) + 1e-5f);
    float4 gg = *(const float4*)&g[tid * 4];
    float4 bb = *(const float4*)&bta[tid * 4];
    float y0 = dx  * inv * gg.x + bb.x;
    float y1 = dyv * inv * gg.y + bb.y;
    float y2 = dz  * inv * gg.z + bb.z;
    float y3 = dw  * inv * gg.w + bb.w;
    uint32_t h0, l0, h1, l1;
    bf16_split_pack(y0, y1, h0, l0);
    bf16_split_pack(y2, y3, h1, l1);
    size_t o = (size_t)row * 256 + tid * 2;
    xh[o] = h0; xh[o + 1] = h1;
    xl[o] = l0; xl[o + 1] = l1;
}

// ============================================================
// Tensor-core attention (bf16-split, fp32 softmax in smem).
// Block = (qt, h, b): 64 queries x all 257 keys. 256 thr, 8 warps.
// smem words: Qh[2304] Ql[2304] KVh[2304] KVl[2304] Ss fp32[64*260]
// ============================================================
#define QTILES 5
#define ATT_ROW 36
#define ATT_Q   2304
#define ATT_SS_OFF 9216
#define ATTN_SMEM ((9216 + 64 * 260) * 4)

__global__ __launch_bounds__(256) void attn_kernel(
    const uint32_t* __restrict__ qh, const uint32_t* __restrict__ ql,
    const float* __restrict__ temp,
    uint32_t* __restrict__ oh, uint32_t* __restrict__ ol)
{
    extern __shared__ uint32_t sm[];
    uint32_t* Qh  = sm;
    uint32_t* Ql  = sm + ATT_Q;
    uint32_t* KVh = sm + 2 * ATT_Q;
    uint32_t* KVl = sm + 3 * ATT_Q;
    float*    Ss  = (float*)(sm + ATT_SS_OFF);

    int qt = blockIdx.x, h = blockIdx.y, b = blockIdx.z;
    int tid = threadIdx.x, wid = tid >> 5, lane = tid & 31;
    int g = lane >> 2, tig = lane & 3;
    int wq = wid & 3, wsub = wid >> 2;   // wsub = wm (scores) / wd (AV)
    size_t rowbase = (size_t)b * NT * 768;
    int hq = h * 32, hk = 256 + h * 32, hv = 512 + h * 32;
    int nbase = qt * 64;
    float tmp = temp[h];

    // ---- load Q tile (64 rows x 32 words, hi+lo) ----
    #pragma unroll
    for (int i = 0; i < 2; i++) {
        int tk = tid + i * 256;
        int r = tk >> 3, wg = tk & 7;
        int n = nbase + r; if (n > NT - 1) n = NT - 1;
        size_t go = rowbase + (size_t)n * 768 + hq + wg * 4;
        *(uint4*)&Qh[r * ATT_ROW + wg * 4] = *(const uint4*)&qh[go];
        *(uint4*)&Ql[r * ATT_ROW + wg * 4] = *(const uint4*)&ql[go];
    }

    // ---- scores: 4 key tiles of 64 via mma ----
    for (int mc = 0; mc < 256; mc += 64) {
        __syncthreads();
        #pragma unroll
        for (int i = 0; i < 2; i++) {
            int tk = tid + i * 256;
            int r = tk >> 3, wg = tk & 7;
            size_t go = rowbase + (size_t)(mc + r) * 768 + hk + wg * 4;
            *(uint4*)&KVh[r * ATT_ROW + wg * 4] = *(const uint4*)&qh[go];
            *(uint4*)&KVl[r * ATT_ROW + wg * 4] = *(const uint4*)&ql[go];
        }
        __syncthreads();

        float c[4][4] = {};
        #pragma unroll
        for (int ks = 0; ks < 4; ks++) {
            int qr = (wq * 16 + g) * ATT_ROW + ks * 8;
            uint32_t ah[4], al[4];
            ah[0] = Qh[qr + tig];               ah[1] = Qh[qr + 8 * ATT_ROW + tig];
            ah[2] = Qh[qr + tig + 4];           ah[3] = Qh[qr + 8 * ATT_ROW + tig + 4];
            al[0] = Ql[qr + tig];               al[1] = Ql[qr + 8 * ATT_ROW + tig];
            al[2] = Ql[qr + tig + 4];           al[3] = Ql[qr + 8 * ATT_ROW + tig + 4];
            #pragma unroll
            for (int nf = 0; nf < 4; nf++) {
                int kr = (wsub * 32 + nf * 8 + g) * ATT_ROW + ks * 8;
                uint32_t bh2[2] = {KVh[kr + tig], KVh[kr + tig + 4]};
                uint32_t bl2[2] = {KVl[kr + tig], KVl[kr + tig + 4]};
                mma16(c[nf], ah, bl2);
                mma16(c[nf], al, bh2);
                mma16(c[nf], ah, bh2);
            }
        }
        #pragma unroll
        for (int nf = 0; nf < 4; nf++) {
            #pragma unroll
            for (int rh = 0; rh < 2; rh++) {
                int q = wq * 16 + g + rh * 8;
                int n = nbase + q;
                int m = mc + wsub * 32 + nf * 8 + 2 * tig;
                float vx = c[nf][rh * 2] * tmp, vy = c[nf][rh * 2 + 1] * tmp;
                if (m     == n) vx = -INFINITY;
                if (m + 1 == n) vy = -INFINITY;
                *(float2*)&Ss[q * 260 + m] = make_float2(vx, vy);
            }
        }
    }

    // ---- tail scores: key m = 256 (exact fp32 from split) ----
    if (tid < 64) {
        int q = tid;
        int n = nbase + q;
        float s;
        if (n == 256) s = -INFINITY;
        else {
            float acc = 0.f;
            size_t kb2 = rowbase + (size_t)256 * 768 + hk;
            #pragma unroll 8
            for (int j = 0; j < 32; j++) {
                uint32_t qw = Qh[q * ATT_ROW + j], qwl = Ql[q * ATT_ROW + j];
                uint32_t kw = qh[kb2 + j],         kwl = ql[kb2 + j];
                float q0 = bf_lo(qw) + bf_lo(qwl), q1 = bf_hi(qw) + bf_hi(qwl);
                float k0 = bf_lo(kw) + bf_lo(kwl), k1 = bf_hi(kw) + bf_hi(kwl);
                acc += q0 * k0 + q1 * k1;
            }
            s = acc * tmp;
        }
        Ss[q * 260 + 256] = s;
    }
    __syncthreads();

    // ---- softmax (fp32, rows 0..63; each warp owns 8 rows) ----
    {
        for (int r = 0; r < 8; r++) {
            float* row = Ss + (wid * 8 + r) * 260;
            float mx = -INFINITY;
            for (int m = lane; m < NT; m += 32) mx = fmaxf(mx, row[m]);
            #pragma unroll
            for (int s = 16; s > 0; s >>= 1) mx = fmaxf(mx, __shfl_xor_sync(0xffffffffu, mx, s));
            float sum = 0.f;
            for (int m = lane; m < NT; m += 32) { float e = expf(row[m] - mx); row[m] = e; sum += e; }
            #pragma unroll
            for (int s = 16; s > 0; s >>= 1) sum += __shfl_xor_sync(0xffffffffu, sum, s);
            float inv = 1.f / sum;
            for (int m = lane; m < NT; m += 32) row[m] *= inv;
        }
    }

    // ---- O = P @ V over keys 0..255 via mma; tail m=256 fp32 ----
    float o_[4][4] = {};
    for (int mc = 0; mc < 256; mc += 64) {
        __syncthreads();
        // load V tile transposed: Vt[d][m-words], half-stride 72
        __nv_bfloat16* TH = (__nv_bfloat16*)KVh;
        __nv_bfloat16* TL = (__nv_bfloat16*)KVl;
        #pragma unroll
        for (int i = 0; i < 8; i++) {
            int idx = tid + i * 256;
            int m = idx >> 5, j = idx & 31;
            size_t go = rowbase + (size_t)(mc + m) * 768 + hv + j;
            uint32_t wh = qh[go], wl = ql[go];
            TH[(2 * j) * 72 + m]     = __ushort_as_bfloat16((unsigned short)(wh & 0xffff));
            TH[(2 * j + 1) * 72 + m] = __ushort_as_bfloat16((unsigned short)(wh >> 16));
            TL[(2 * j) * 72 + m]     = __ushort_as_bfloat16((unsigned short)(wl & 0xffff));
            TL[(2 * j + 1) * 72 + m] = __ushort_as_bfloat16((unsigned short)(wl >> 16));
        }
        __syncthreads();

        #pragma unroll
        for (int ks = 0; ks < 4; ks++) {
            int q0 = (wq * 16 + g) * 260, q1 = q0 + 8 * 260;
            int mb = mc + ks * 16 + 2 * tig;
            uint32_t ah[4], al[4];
            bf16_split_pack(Ss[q0 + mb],     Ss[q0 + mb + 1],     ah[0], al[0]);
            bf16_split_pack(Ss[q1 + mb],     Ss[q1 + mb + 1],     ah[1], al[1]);
            bf16_split_pack(Ss[q0 + mb + 8], Ss[q0 + mb + 9],     ah[2], al[2]);
            bf16_split_pack(Ss[q1 + mb + 8], Ss[q1 + mb + 9],     ah[3], al[3]);
            #pragma unroll
            for (int nf = 0; nf < 4; nf++) {
                int vr = (wsub * 32 + nf * 8 + g) * ATT_ROW + ks * 8;
                uint32_t bh2[2] = {KVh[vr + tig], KVh[vr + tig + 4]};
                uint32_t bl2[2] = {KVl[vr + tig], KVl[vr + tig + 4]};
                mma16(o_[nf], ah, bl2);
                mma16(o_[nf], al, bh2);
                mma16(o_[nf], ah, bh2);
            }
        }
    }
    // tail: key 256
    {
        int q0 = wq * 16 + g;
        float p0 = Ss[q0 * 260 + 256];
        float p1 = Ss[(q0 + 8) * 260 + 256];
        size_t vb = rowbase + (size_t)256 * 768 + hv;
        #pragma unroll
        for (int nf = 0; nf < 4; nf++) {
            int dw = wsub * 16 + nf * 4 + tig;
            uint32_t wh = qh[vb + dw], wl = ql[vb + dw];
            float v0 = bf_lo(wh) + bf_lo(wl);
            float v1 = bf_hi(wh) + bf_hi(wl);
            o_[nf][0] += p0 * v0; o_[nf][1] += p0 * v1;
            o_[nf][2] += p1 * v0; o_[nf][3] += p1 * v1;
        }
    }
    // ---- write O split-packed ----
    #pragma unroll
    for (int rh = 0; rh < 2; rh++) {
        int n = nbase + wq * 16 + g + rh * 8;
        if (n < NT) {
            #pragma unroll
            for (int nf = 0; nf < 4; nf++) {
                uint32_t hw_, lw_;
                bf16_split_pack(o_[nf][rh * 2], o_[nf][rh * 2 + 1], hw_, lw_);
                size_t off = (size_t)(b * NT + n) * 256 + h * 32 + wsub * 16 + nf * 4 + tig;
                oh[off] = hw_; ol[off] = lw_;
            }
        }
    }
}

// ============================================================
// cls row init
// ============================================================
__global__ void cls_kernel(const float* __restrict__ cls, const float* __restrict__ pos,
                           float* __restrict__ tok)
{
    int idx = blockIdx.x * blockDim.x + threadIdx.x;
    if (idx >= Bq * Dm) return;
    int d = idx & 511, b = idx >> 9;
    tok[(size_t)b * NT * Dm + d] = cls[d] + pos[d];
}

// ============================================================
// Head
// ============================================================
__global__ void head_kernel(const float* __restrict__ tok, const float* __restrict__ ng,
                            const float* __restrict__ nb, const float* __restrict__ hw,
                            const float* __restrict__ hb, float* __restrict__ out)
{
    int b = blockIdx.x, tid = threadIdx.x;
    __shared__ float red[128];
    const float* xr = tok + (size_t)b * NT * Dm;
    float v[4]; float s = 0.f;
    #pragma unroll
    for (int i = 0; i < 4; i++) { v[i] = xr[tid + 128 * i]; s += v[i]; }
    red[tid] = s; __syncthreads();
    for (int st = 64; st > 0; st >>= 1) { if (tid < st) red[tid] += red[tid + st]; __syncthreads(); }
    float mu = red[0] * (1.f / 512.f); __syncthreads();
    float s2 = 0.f;
    #pragma unroll
    for (int i = 0; i < 4; i++) { float dv = v[i] - mu; s2 += dv * dv; }
    red[tid] = s2; __syncthreads();
    for (int st = 64; st > 0; st >>= 1) { if (tid < st) red[tid] += red[tid + st]; __syncthreads(); }
    float inv = rsqrtf(red[0] * (1.f / 512.f) + 1e-5f);
    __syncthreads();

    float xn[4];
    #pragma unroll
    for (int i = 0; i < 4; i++) {
        int idx = tid + 128 * i;
        xn[i] = (v[i] - mu) * inv * ng[idx] + nb[idx];
    }

    for (int c = 0; c < 3; c++) {
        float p = 0.f;
        #pragma unroll
        for (int i = 0; i < 4; i++) {
            int idx = tid + 128 * i;
            p = fmaf(xn[i], hw[idx * 3 + c], p);
        }
        red[tid] = p; __syncthreads();
        for (int st = 64; st > 0; st >>= 1) { if (tid < st) red[tid] += red[tid + st]; __syncthreads(); }
        if (tid == 0) out[b * 3 + c] = red[0] + hb[c];
        __syncthreads();
    }
}

// ============================================================
// Launch
// ============================================================
static uint32_t* s_wTh = nullptr;
static uint32_t* s_wTl = nullptr;

static inline void launch_gemm(const uint32_t* Ah, const uint32_t* Al, size_t wOffW,
                               const float* bias, const float* res,
                               float* C, uint32_t* Ch, uint32_t* Cl,
                               const float* comb, const float* pos, float* tokout,
                               int M, int Nn, int K, int act)
{
    dim3 grid(Nn / 128, (M + 127) / 128);
    mma_gemm<<<grid, 256, GEMM_SMEM_BYTES>>>(Ah, Al, s_wTh + wOffW, s_wTl + wOffW,
                                             bias, res, C, Ch, Cl, comb, pos, tokout,
                                             M, Nn, K, act);
}

extern "C" void kernel_launch(void* const* d_in, const int* in_sizes, int n_in,
                              void* d_out, int out_size)
{
    const float* image   = (const float*)d_in[0];
    const float* ssw     = (const float*)d_in[1];
    const float* ssb     = (const float*)d_in[2];
    const float* ssg     = (const float*)d_in[3];
    const float* ssbeta  = (const float*)d_in[4];
    const float* sow     = (const float*)d_in[5];
    const float* sob     = (const float*)d_in[6];
    const float* sog     = (const float*)d_in[7];
    const float* sobeta  = (const float*)d_in[8];
    const float* fw      = (const float*)d_in[9];
    const float* fb      = (const float*)d_in[10];
    const float* cls     = (const float*)d_in[11];
    const float* pos     = (const float*)d_in[12];
    const float* ln1g    = (const float*)d_in[13];
    const float* ln1b    = (const float*)d_in[14];
    const float* qkvw    = (const float*)d_in[15];
    const float* qkvb    = (const float*)d_in[16];
    const float* projw   = (const float*)d_in[17];
    const float* projb   = (const float*)d_in[18];
    const float* temp    = (const float*)d_in[19];
    const float* ln2g    = (const float*)d_in[20];
    const float* ln2b    = (const float*)d_in[21];
    const float* w1      = (const float*)d_in[22];
    const float* b1      = (const float*)d_in[23];
    const float* w2      = (const float*)d_in[24];
    const float* b2      = (const float*)d_in[25];
    const float* ng      = (const float*)d_in[26];
    const float* nb      = (const float*)d_in[27];
    const float* hw      = (const float*)d_in[28];
    const float* hb      = (const float*)d_in[29];

    float *comb, *tok;
    uint32_t *combh, *combl, *xh, *xl, *qkvh, *qkvl, *oh, *ol, *hh, *hl;
    cudaGetSymbolAddress((void**)&comb,  g_comb);
    cudaGetSymbolAddress((void**)&tok,   g_tok);
    cudaGetSymbolAddress((void**)&combh, g_combh);
    cudaGetSymbolAddress((void**)&combl, g_combl);
    cudaGetSymbolAddress((void**)&xh,    g_xh);
    cudaGetSymbolAddress((void**)&xl,    g_xl);
    cudaGetSymbolAddress((void**)&qkvh,  g_qkvh);
    cudaGetSymbolAddress((void**)&qkvl,  g_qkvl);
    cudaGetSymbolAddress((void**)&oh,    g_oh);
    cudaGetSymbolAddress((void**)&ol,    g_ol);
    cudaGetSymbolAddress((void**)&hh,    g_hh);
    cudaGetSymbolAddress((void**)&hl,    g_hl);
    cudaGetSymbolAddress((void**)&s_wTh, g_wTh);
    cudaGetSymbolAddress((void**)&s_wTl, g_wTl);

    cudaFuncSetAttribute(mma_gemm, cudaFuncAttributeMaxDynamicSharedMemorySize, GEMM_SMEM_BYTES);
    cudaFuncSetAttribute(attn_kernel, cudaFuncAttributeMaxDynamicSharedMemorySize, ATTN_SMEM);

    const int Mtok = Bq * NT;   // 8224
    const int Mpat = Bq * NP;   // 8192

    // launch 0: cls init
    cls_kernel<<<(Bq * Dm + 255) / 256, 256>>>(cls, pos, tok);
    // launch 1: weight transposes
    transpose_all<<<25088, 256>>>(fw, qkvw, projw, w1, w2, s_wTh, s_wTl);
    // launch 2: SPT
    spt_kernel<<<Mpat, 512>>>(image, ssw, ssb, ssg, ssbeta,
                              sow, sob, sog, sobeta, comb, combh, combl);
    // launch 3: gate GEMM with fused token-mix epilogue  <-- profiled slot
    launch_gemm(combh, combl, FWT_OFFW, fb, nullptr, nullptr, nullptr, nullptr,
                comb, pos, tok, Mpat, Dm, 2 * Dm, /*gate-fuse*/3);

    for (int l = 0; l < NL; l++) {
        size_t lb = LAYER_OFFW(l);
        ln_kernel<<<Mtok, 128>>>(tok, ln1g + l * Dm, ln1b + l * Dm, xh, xl);
        // qkv GEMM -> split-packed output for tensor attention
        launch_gemm(xh, xl, lb + QKVT_OFFW, qkvb + l * 3 * Dm, nullptr,
                    nullptr, qkvh, qkvl, nullptr, nullptr, nullptr, Mtok, 3 * Dm, Dm, 0);
        attn_kernel<<<dim3(QTILES, NH, Bq), 256, ATTN_SMEM>>>(qkvh, qkvl, temp + l * NH, oh, ol);
        launch_gemm(oh, ol, lb + PROJT_OFFW, projb + l * Dm, tok,
                    tok, nullptr, nullptr, nullptr, nullptr, nullptr, Mtok, Dm, Dm, 0);
        ln_kernel<<<Mtok, 128>>>(tok, ln2g + l * Dm, ln2b + l * Dm, xh, xl);
        launch_gemm(xh, xl, lb + W1T_OFFW, b1 + l * MLPD, nullptr,
                    nullptr, hh, hl, nullptr, nullptr, nullptr, Mtok, MLPD, Dm, /*gelu*/2);
        launch_gemm(hh, hl, lb + W2T_OFFW, b2 + l * Dm, tok,
                    tok, nullptr, nullptr, nullptr, nullptr, nullptr, Mtok, Dm, MLPD, 0);
    }

    head_kernel<<<Bq, 128>>>(tok, ng, nb, hw, hb, (float*)d_out);
}

// round 14
// speedup vs baseline: 1.1157x; 1.0362x over previous
#include <cuda_runtime.h>
#include <cuda_bf16.h>
#include <math.h>
#include <stdint.h>

// ---- model constants ----
#define Bq   32
#define IMGS 128
#define Dm   512
#define NH   8
#define NL   8
#define MLPD 2048
#define NP   256
#define NT   257
#define HDm  64

// ---- scratch (device globals; no allocation allowed) ----
__device__ float g_comb[Bq * NP * 2 * Dm];
__device__ float g_tok [Bq * NT * Dm];
__device__ uint32_t g_combh[Bq * NP * 512];
__device__ uint32_t g_combl[Bq * NP * 512];
__device__ uint32_t g_xh[Bq * NT * 256];
__device__ uint32_t g_xl[Bq * NT * 256];
__device__ uint32_t g_qkvh[Bq * NT * 768];
__device__ uint32_t g_qkvl[Bq * NT * 768];
__device__ uint32_t g_oh[Bq * NT * 256];
__device__ uint32_t g_ol[Bq * NT * 256];
__device__ uint32_t g_hh[Bq * NT * 1024];
__device__ uint32_t g_hl[Bq * NT * 1024];
#define WT_ELEMS (512*1024 + NL * (1536*512 + 512*512 + 2048*512 + 512*2048))
__device__ uint32_t g_wTh[WT_ELEMS / 2];
__device__ uint32_t g_wTl[WT_ELEMS / 2];

#define FWT_OFFW    0
#define LAYER_OFFW(l) (262144 + (size_t)(l) * 1572864)
#define QKVT_OFFW   0
#define PROJT_OFFW  393216
#define W1T_OFFW    524288
#define W2T_OFFW    1048576

__device__ __forceinline__ void bf16_split_pack(float v0, float v1,
                                                uint32_t& hw, uint32_t& lw) {
    __nv_bfloat16 h0 = __float2bfloat16(v0), h1 = __float2bfloat16(v1);
    float r0 = v0 - __bfloat162float(h0);
    float r1 = v1 - __bfloat162float(h1);
    __nv_bfloat16 l0 = __float2bfloat16(r0), l1 = __float2bfloat16(r1);
    hw = (uint32_t)__bfloat16_as_ushort(h0) | ((uint32_t)__bfloat16_as_ushort(h1) << 16);
    lw = (uint32_t)__bfloat16_as_ushort(l0) | ((uint32_t)__bfloat16_as_ushort(l1) << 16);
}
__device__ __forceinline__ float bf_lo(uint32_t w) {
    return __bfloat162float(__ushort_as_bfloat16((unsigned short)(w & 0xffff)));
}
__device__ __forceinline__ float bf_hi(uint32_t w) {
    return __bfloat162float(__ushort_as_bfloat16((unsigned short)(w >> 16)));
}

__device__ __forceinline__ void mma16(float c[4], const uint32_t a[4], const uint32_t b[2]) {
    asm volatile(
        "mma.sync.aligned.m16n8k16.row.col.f32.bf16.bf16.f32 "
        "{%0,%1,%2,%3}, {%4,%5,%6,%7}, {%8,%9}, {%0,%1,%2,%3};"
        : "+f"(c[0]), "+f"(c[1]), "+f"(c[2]), "+f"(c[3])
        : "r"(a[0]), "r"(a[1]), "r"(a[2]), "r"(a[3]), "r"(b[0]), "r"(b[1]));
}

__device__ __forceinline__ void ldm4(uint32_t& r0, uint32_t& r1, uint32_t& r2, uint32_t& r3,
                                     uint32_t addr) {
    asm volatile("ldmatrix.sync.aligned.m8n8.x4.shared.b16 {%0,%1,%2,%3}, [%4];"
                 : "=r"(r0), "=r"(r1), "=r"(r2), "=r"(r3) : "r"(addr));
}

__device__ __forceinline__ void cp16(uint32_t dst, const void* src) {
    asm volatile("cp.async.cg.shared.global [%0], [%1], 16;" :: "r"(dst), "l"(src));
}

// ================= GEMM =================
#define AS_W 12
#define ARR_W 1536
#define BUFSTRIDE_W 6144
#define NSTAGE 4
#define GEMM_SMEM_BYTES (NSTAGE * BUFSTRIDE_W * 4)

__global__ __launch_bounds__(256, 2) void mma_gemm(
    const uint32_t* __restrict__ Ah, const uint32_t* __restrict__ Al,
    const uint32_t* __restrict__ BTh, const uint32_t* __restrict__ BTl,
    const float* __restrict__ bias, const float* __restrict__ res,
    float* __restrict__ C, uint32_t* __restrict__ Ch, uint32_t* __restrict__ Cl,
    const float* __restrict__ comb, const float* __restrict__ pos,
    float* __restrict__ tokout,
    int M, int N, int K, int act)
{
    extern __shared__ uint32_t smu[];
    int tid = threadIdx.x;
    int wid = tid >> 5, lane = tid & 31;
    int g = lane >> 2, tig = lane & 3;
    int m0 = blockIdx.y * 128, n0 = blockIdx.x * 128;
    int wmi = wid & 3, wni = wid >> 2;
    int Kw = K >> 1;

    int lr = tid >> 1, lw4 = (tid & 1) * 4;
    int gma = m0 + lr; if (gma > M - 1) gma = M - 1;
    size_t aoff = (size_t)gma * Kw + lw4;
    size_t boff = (size_t)(n0 + lr) * Kw + lw4;
    uint32_t sbase = (uint32_t)__cvta_generic_to_shared(smu);
    uint32_t sdb = sbase + (uint32_t)(lr * AS_W + lw4) * 4;

    // ldmatrix per-lane row offsets (bytes within an array)
    // A x4: lanes 0-15 -> rows 0-15 (khalf0), lanes 16-31 -> rows 0-15 (khalf1)
    uint32_t a_lm = (uint32_t)((wmi * 32 + (lane & 15)) * 48 + (lane >> 4) * 16);
    // B x4: nf_sel=(lane>>4)&1 (8-row block), khalf=(lane>>3)&1
    uint32_t b_lm = (uint32_t)((wni * 64 + ((lane >> 4) & 1) * 8 + (lane & 7)) * 48
                               + ((lane >> 3) & 1) * 16);

    float c[2][8][4] = {};
    int ntiles = K >> 4;

#define ISSUE(T) do {                                                         \
        uint32_t d = sdb + ((T) & (NSTAGE - 1)) * (BUFSTRIDE_W * 4);          \
        size_t ko = (size_t)(T) * 8;                                          \
        cp16(d,                 Ah  + aoff + ko);                             \
        cp16(d + ARR_W * 4,     Al  + aoff + ko);                             \
        cp16(d + ARR_W * 8,     BTh + boff + ko);                             \
        cp16(d + ARR_W * 12,    BTl + boff + ko);                             \
        asm volatile("cp.async.commit_group;" ::: "memory");                  \
    } while (0)

    #pragma unroll
    for (int s = 0; s < NSTAGE - 1; s++) ISSUE(s);

    for (int t = 0; t < ntiles; t++) {
        int rem = ntiles - 1 - t;
        if (rem >= 2)      asm volatile("cp.async.wait_group 2;" ::: "memory");
        else if (rem == 1) asm volatile("cp.async.wait_group 1;" ::: "memory");
        else               asm volatile("cp.async.wait_group 0;" ::: "memory");
        __syncthreads();

        if (t + NSTAGE - 1 < ntiles) ISSUE(t + NSTAGE - 1);

        uint32_t bufb = sbase + (uint32_t)((t & (NSTAGE - 1)) * BUFSTRIDE_W * 4);
        uint32_t AhB = bufb,                AlB = bufb + ARR_W * 4;
        uint32_t BhB = bufb + ARR_W * 8,    BlB = bufb + ARR_W * 12;

        uint32_t afh[2][4], afl[2][4];
        #pragma unroll
        for (int mf = 0; mf < 2; mf++) {
            uint32_t ra = a_lm + (uint32_t)(mf * 16 * 48);
            ldm4(afh[mf][0], afh[mf][1], afh[mf][2], afh[mf][3], AhB + ra);
            ldm4(afl[mf][0], afl[mf][1], afl[mf][2], afl[mf][3], AlB + ra);
        }
        #pragma unroll
        for (int nfp = 0; nfp < 4; nfp++) {
            uint32_t rb = b_lm + (uint32_t)(nfp * 16 * 48);
            uint32_t bh[4], bl[4];
            ldm4(bh[0], bh[1], bh[2], bh[3], BhB + rb);
            ldm4(bl[0], bl[1], bl[2], bl[3], BlB + rb);
            #pragma unroll
            for (int s = 0; s < 2; s++) {
                int nf = nfp * 2 + s;
                uint32_t bh2[2] = {bh[s * 2], bh[s * 2 + 1]};
                uint32_t bl2[2] = {bl[s * 2], bl[s * 2 + 1]};
                #pragma unroll
                for (int mf = 0; mf < 2; mf++) {
                    mma16(c[mf][nf], afh[mf], bl2);
                    mma16(c[mf][nf], afl[mf], bh2);
                    mma16(c[mf][nf], afh[mf], bh2);
                }
            }
        }
    }
#undef ISSUE

    int wm = wmi * 32, wn = wni * 64;
    int Nw = N >> 1;
    #pragma unroll
    for (int mf = 0; mf < 2; mf++) {
        #pragma unroll
        for (int rh = 0; rh < 2; rh++) {
            int m = m0 + wm + mf * 16 + g + rh * 8;
            if (m >= M) continue;
            #pragma unroll
            for (int nf = 0; nf < 8; nf++) {
                int n = n0 + wn + nf * 8 + 2 * tig;
                float vx = c[mf][nf][rh * 2], vy = c[mf][nf][rh * 2 + 1];
                if (bias) {
                    float2 bb = *(const float2*)&bias[n];
                    vx += bb.x; vy += bb.y;
                }
                if (act == 1) {
                    vx = 1.f / (1.f + expf(-vx));
                    vy = 1.f / (1.f + expf(-vy));
                } else if (act == 2) {
                    vx = 0.5f * vx * (1.f + erff(vx * 0.70710678118654752f));
                    vy = 0.5f * vy * (1.f + erff(vy * 0.70710678118654752f));
                } else if (act == 3) {
                    float gx = 1.f / (1.f + expf(-vx));
                    float gy = 1.f / (1.f + expf(-vy));
                    size_t mr = (size_t)m * 1024;
                    float2 sv = *(const float2*)&comb[mr + n];
                    float2 ov = *(const float2*)&comb[mr + 512 + n];
                    int p = m & 255, b = m >> 8;
                    float2 pp = *(const float2*)&pos[(size_t)(1 + p) * Dm + n];
                    float ox = gx * sv.x + (1.f - gx) * ov.x + pp.x;
                    float oy = gy * sv.y + (1.f - gy) * ov.y + pp.y;
                    *(float2*)&tokout[((size_t)(b * NT + 1 + p)) * Dm + n] = make_float2(ox, oy);
                    continue;
                }
                if (res) {
                    float2 rr = *(const float2*)&res[(size_t)m * N + n];
                    vx += rr.x; vy += rr.y;
                }
                if (C) *(float2*)&C[(size_t)m * N + n] = make_float2(vx, vy);
                if (Ch) {
                    uint32_t hw_, lw_;
                    bf16_split_pack(vx, vy, hw_, lw_);
                    size_t o = (size_t)m * Nw + (n >> 1);
                    Ch[o] = hw_; Cl[o] = lw_;
                }
            }
        }
    }
}

// ============================================================
// ALL weight transposes in ONE launch
// ============================================================
__global__ void transpose_all(const float* __restrict__ fw,
                              const float* __restrict__ qkvw,
                              const float* __restrict__ projw,
                              const float* __restrict__ w1,
                              const float* __restrict__ w2,
                              uint32_t* __restrict__ dsth,
                              uint32_t* __restrict__ dstl)
{
    int id = blockIdx.x;
    const float* src; int K, N; size_t base; int loc;
    if (id < 512) { src = fw; K = 1024; N = 512; base = 0; loc = id; }
    else {
        int t = id - 512, l = t / 3072, r = t % 3072;
        size_t L = LAYER_OFFW(l);
        if (r < 768)       { src = qkvw  + (size_t)l * 786432;  K = 512;  N = 1536; base = L;               loc = r; }
        else if (r < 1024) { src = projw + (size_t)l * 262144;  K = 512;  N = 512;  base = L + PROJT_OFFW;  loc = r - 768; }
        else if (r < 2048) { src = w1    + (size_t)l * 1048576; K = 512;  N = 2048; base = L + W1T_OFFW;    loc = r - 1024; }
        else               { src = w2    + (size_t)l * 1048576; K = 2048; N = 512;  base = L + W2T_OFFW;    loc = r - 2048; }
    }
    int ntx = N >> 5;
    int kb = (loc / ntx) << 5, nb = (loc % ntx) << 5;

    __shared__ float t[32][33];
    int tx = threadIdx.x & 31, ty = threadIdx.x >> 5;
    #pragma unroll
    for (int j = 0; j < 32; j += 8)
        t[ty + j][tx] = src[(size_t)(kb + ty + j) * N + nb + tx];
    __syncthreads();

    int w = threadIdx.x & 15, r2 = threadIdx.x >> 4;
    int Kw = K >> 1;
    #pragma unroll
    for (int j = 0; j < 32; j += 16) {
        int row = r2 + j;
        float v0 = t[2 * w][row], v1 = t[2 * w + 1][row];
        uint32_t hw_, lw_; bf16_split_pack(v0, v1, hw_, lw_);
        size_t o = base + (size_t)(nb + row) * Kw + (kb >> 1) + w;
        dsth[o] = hw_; dstl[o] = lw_;
    }
}

// ============================================================
// SPT
// ============================================================
__device__ __forceinline__ float ln512(float a, float* red, int tid) {
    red[tid] = a; __syncthreads();
    for (int s = 256; s > 0; s >>= 1) { if (tid < s) red[tid] += red[tid + s]; __syncthreads(); }
    float mu = red[0] * (1.f / 512.f); __syncthreads();
    float dv = a - mu;
    red[tid] = dv * dv; __syncthreads();
    for (int s = 256; s > 0; s >>= 1) { if (tid < s) red[tid] += red[tid + s]; __syncthreads(); }
    float var = red[0] * (1.f / 512.f); __syncthreads();
    return dv * rsqrtf(var + 1e-5f);
}

__global__ void spt_kernel(const float* __restrict__ img,
    const float* __restrict__ w0, const float* __restrict__ bb0,
    const float* __restrict__ gg0, const float* __restrict__ be0,
    const float* __restrict__ w1, const float* __restrict__ bb1,
    const float* __restrict__ gg1, const float* __restrict__ be1,
    float* __restrict__ comb, uint32_t* __restrict__ combh, uint32_t* __restrict__ combl)
{
    int blk = blockIdx.x;
    int b = blk >> 8;
    int p = blk & 255;
    int py = p >> 4, px = p & 15;

    __shared__ float patch[10][10];
    __shared__ float red[512];
    int tid = threadIdx.x;

    if (tid < 100) {
        int r = tid / 10, c = tid % 10;
        int ir = (py * 8 - 1 + r) & 127;
        int ic = (px * 8 - 1 + c) & 127;
        patch[r][c] = img[((size_t)b * IMGS + ir) * IMGS + ic];
    }
    __syncthreads();

    const int dy[5] = {1, 0, 2, 0, 2};
    const int dx[5] = {1, 0, 0, 2, 2};

    int d = tid;
    float a0 = bb0[d], a1 = bb1[d];
    const float* wp0 = w0 + (size_t)d * 320;
    const float* wp1 = w1 + (size_t)d * 320;

    for (int c = 0; c < 5; c++) {
        #pragma unroll
        for (int i = 0; i < 8; i++) {
            #pragma unroll
            for (int j = 0; j < 8; j++) {
                float xv = patch[i + dy[c]][j + dx[c]];
                int wi = (c * 8 + i) * 8 + j;
                a0 = fmaf(wp0[wi], xv, a0);
                a1 = fmaf(wp1[wi], xv, a1);
            }
        }
    }

    float n0 = ln512(a0, red, tid) * gg0[d] + be0[d];
    float n1 = ln512(a1, red, tid) * gg1[d] + be1[d];

    size_t row = blk;
    comb[row * 1024 + d]       = n0;
    comb[row * 1024 + 512 + d] = n1;

    red[tid] = n0; __syncthreads();
    if (tid < 256) {
        uint32_t h, l; bf16_split_pack(red[2 * tid], red[2 * tid + 1], h, l);
        combh[row * 512 + tid] = h; combl[row * 512 + tid] = l;
    }
    __syncthreads();
    red[tid] = n1; __syncthreads();
    if (tid < 256) {
        uint32_t h, l; bf16_split_pack(red[2 * tid], red[2 * tid + 1], h, l);
        combh[row * 512 + 256 + tid] = h; combl[row * 512 + 256 + tid] = l;
    }
}

// ============================================================
// LayerNorm over D=512 -> split-packed output
// ============================================================
__global__ void ln_kernel(const float* __restrict__ in, const float* __restrict__ g,
                          const float* __restrict__ bta,
                          uint32_t* __restrict__ xh, uint32_t* __restrict__ xl)
{
    int row = blockIdx.x, tid = threadIdx.x;
    __shared__ float red[128];
    float4 v = *(const float4*)&in[(size_t)row * Dm + tid * 4];
    red[tid] = v.x + v.y + v.z + v.w; __syncthreads();
    for (int st = 64; st > 0; st >>= 1) { if (tid < st) red[tid] += red[tid + st]; __syncthreads(); }
    float mu = red[0] * (1.f / 512.f); __syncthreads();
    float dx = v.x - mu, dyv = v.y - mu, dz = v.z - mu, dw = v.w - mu;
    red[tid] = dx * dx + dyv * dyv + dz * dz + dw * dw; __syncthreads();
    for (int st = 64; st > 0; st >>= 1) { if (tid < st) red[tid] += red[tid + st]; __syncthreads(); }
    float inv = rsqrtf(red[0] * (1.f / 512.f) + 1e-5f);
    float4 gg = *(const float4*)&g[tid * 4];
    float4 bb = *(const float4*)&bta[tid * 4];
    float y0 = dx  * inv * gg.x + bb.x;
    float y1 = dyv * inv * gg.y + bb.y;
    float y2 = dz  * inv * gg.z + bb.z;
    float y3 = dw  * inv * gg.w + bb.w;
    uint32_t h0, l0, h1, l1;
    bf16_split_pack(y0, y1, h0, l0);
    bf16_split_pack(y2, y3, h1, l1);
    size_t o = (size_t)row * 256 + tid * 2;
    xh[o] = h0; xh[o + 1] = h1;
    xl[o] = l0; xl[o + 1] = l1;
}

// ============================================================
// Tensor-core attention (R13, proven)
// ============================================================
#define QTILES 5
#define ATT_ROW 36
#define ATT_Q   2304
#define ATT_SS_OFF 9216
#define ATTN_SMEM ((9216 + 64 * 260) * 4)

__global__ __launch_bounds__(256) void attn_kernel(
    const uint32_t* __restrict__ qh, const uint32_t* __restrict__ ql,
    const float* __restrict__ temp,
    uint32_t* __restrict__ oh, uint32_t* __restrict__ ol)
{
    extern __shared__ uint32_t sm[];
    uint32_t* Qh  = sm;
    uint32_t* Ql  = sm + ATT_Q;
    uint32_t* KVh = sm + 2 * ATT_Q;
    uint32_t* KVl = sm + 3 * ATT_Q;
    float*    Ss  = (float*)(sm + ATT_SS_OFF);

    int qt = blockIdx.x, h = blockIdx.y, b = blockIdx.z;
    int tid = threadIdx.x, wid = tid >> 5, lane = tid & 31;
    int g = lane >> 2, tig = lane & 3;
    int wq = wid & 3, wsub = wid >> 2;
    size_t rowbase = (size_t)b * NT * 768;
    int hq = h * 32, hk = 256 + h * 32, hv = 512 + h * 32;
    int nbase = qt * 64;
    float tmp = temp[h];

    #pragma unroll
    for (int i = 0; i < 2; i++) {
        int tk = tid + i * 256;
        int r = tk >> 3, wg = tk & 7;
        int n = nbase + r; if (n > NT - 1) n = NT - 1;
        size_t go = rowbase + (size_t)n * 768 + hq + wg * 4;
        *(uint4*)&Qh[r * ATT_ROW + wg * 4] = *(const uint4*)&qh[go];
        *(uint4*)&Ql[r * ATT_ROW + wg * 4] = *(const uint4*)&ql[go];
    }

    for (int mc = 0; mc < 256; mc += 64) {
        __syncthreads();
        #pragma unroll
        for (int i = 0; i < 2; i++) {
            int tk = tid + i * 256;
            int r = tk >> 3, wg = tk & 7;
            size_t go = rowbase + (size_t)(mc + r) * 768 + hk + wg * 4;
            *(uint4*)&KVh[r * ATT_ROW + wg * 4] = *(const uint4*)&qh[go];
            *(uint4*)&KVl[r * ATT_ROW + wg * 4] = *(const uint4*)&ql[go];
        }
        __syncthreads();

        float c[4][4] = {};
        #pragma unroll
        for (int ks = 0; ks < 4; ks++) {
            int qr = (wq * 16 + g) * ATT_ROW + ks * 8;
            uint32_t ah[4], al[4];
            ah[0] = Qh[qr + tig];               ah[1] = Qh[qr + 8 * ATT_ROW + tig];
            ah[2] = Qh[qr + tig + 4];           ah[3] = Qh[qr + 8 * ATT_ROW + tig + 4];
            al[0] = Ql[qr + tig];               al[1] = Ql[qr + 8 * ATT_ROW + tig];
            al[2] = Ql[qr + tig + 4];           al[3] = Ql[qr + 8 * ATT_ROW + tig + 4];
            #pragma unroll
            for (int nf = 0; nf < 4; nf++) {
                int kr = (wsub * 32 + nf * 8 + g) * ATT_ROW + ks * 8;
                uint32_t bh2[2] = {KVh[kr + tig], KVh[kr + tig + 4]};
                uint32_t bl2[2] = {KVl[kr + tig], KVl[kr + tig + 4]};
                mma16(c[nf], ah, bl2);
                mma16(c[nf], al, bh2);
                mma16(c[nf], ah, bh2);
            }
        }
        #pragma unroll
        for (int nf = 0; nf < 4; nf++) {
            #pragma unroll
            for (int rh = 0; rh < 2; rh++) {
                int q = wq * 16 + g + rh * 8;
                int n = nbase + q;
                int m = mc + wsub * 32 + nf * 8 + 2 * tig;
                float vx = c[nf][rh * 2] * tmp, vy = c[nf][rh * 2 + 1] * tmp;
                if (m     == n) vx = -INFINITY;
                if (m + 1 == n) vy = -INFINITY;
                *(float2*)&Ss[q * 260 + m] = make_float2(vx, vy);
            }
        }
    }

    if (tid < 64) {
        int q = tid;
        int n = nbase + q;
        float s;
        if (n == 256) s = -INFINITY;
        else {
            float acc = 0.f;
            size_t kb2 = rowbase + (size_t)256 * 768 + hk;
            #pragma unroll 8
            for (int j = 0; j < 32; j++) {
                uint32_t qw = Qh[q * ATT_ROW + j], qwl = Ql[q * ATT_ROW + j];
                uint32_t kw = qh[kb2 + j],         kwl = ql[kb2 + j];
                float q0 = bf_lo(qw) + bf_lo(qwl), q1 = bf_hi(qw) + bf_hi(qwl);
                float k0 = bf_lo(kw) + bf_lo(kwl), k1 = bf_hi(kw) + bf_hi(kwl);
                acc += q0 * k0 + q1 * k1;
            }
            s = acc * tmp;
        }
        Ss[q * 260 + 256] = s;
    }
    __syncthreads();

    {
        for (int r = 0; r < 8; r++) {
            float* row = Ss + (wid * 8 + r) * 260;
            float mx = -INFINITY;
            for (int m = lane; m < NT; m += 32) mx = fmaxf(mx, row[m]);
            #pragma unroll
            for (int s = 16; s > 0; s >>= 1) mx = fmaxf(mx, __shfl_xor_sync(0xffffffffu, mx, s));
            float sum = 0.f;
            for (int m = lane; m < NT; m += 32) { float e = expf(row[m] - mx); row[m] = e; sum += e; }
            #pragma unroll
            for (int s = 16; s > 0; s >>= 1) sum += __shfl_xor_sync(0xffffffffu, sum, s);
            float inv = 1.f / sum;
            for (int m = lane; m < NT; m += 32) row[m] *= inv;
        }
    }

    float o_[4][4] = {};
    for (int mc = 0; mc < 256; mc += 64) {
        __syncthreads();
        __nv_bfloat16* TH = (__nv_bfloat16*)KVh;
        __nv_bfloat16* TL = (__nv_bfloat16*)KVl;
        #pragma unroll
        for (int i = 0; i < 8; i++) {
            int idx = tid + i * 256;
            int m = idx >> 5, j = idx & 31;
            size_t go = rowbase + (size_t)(mc + m) * 768 + hv + j;
            uint32_t wh = qh[go], wl = ql[go];
            TH[(2 * j) * 72 + m]     = __ushort_as_bfloat16((unsigned short)(wh & 0xffff));
            TH[(2 * j + 1) * 72 + m] = __ushort_as_bfloat16((unsigned short)(wh >> 16));
            TL[(2 * j) * 72 + m]     = __ushort_as_bfloat16((unsigned short)(wl & 0xffff));
            TL[(2 * j + 1) * 72 + m] = __ushort_as_bfloat16((unsigned short)(wl >> 16));
        }
        __syncthreads();

        #pragma unroll
        for (int ks = 0; ks < 4; ks++) {
            int q0 = (wq * 16 + g) * 260, q1 = q0 + 8 * 260;
            int mb = mc + ks * 16 + 2 * tig;
            uint32_t ah[4], al[4];
            bf16_split_pack(Ss[q0 + mb],     Ss[q0 + mb + 1],     ah[0], al[0]);
            bf16_split_pack(Ss[q1 + mb],     Ss[q1 + mb + 1],     ah[1], al[1]);
            bf16_split_pack(Ss[q0 + mb + 8], Ss[q0 + mb + 9],     ah[2], al[2]);
            bf16_split_pack(Ss[q1 + mb + 8], Ss[q1 + mb + 9],     ah[3], al[3]);
            #pragma unroll
            for (int nf = 0; nf < 4; nf++) {
                int vr = (wsub * 32 + nf * 8 + g) * ATT_ROW + ks * 8;
                uint32_t bh2[2] = {KVh[vr + tig], KVh[vr + tig + 4]};
                uint32_t bl2[2] = {KVl[vr + tig], KVl[vr + tig + 4]};
                mma16(o_[nf], ah, bl2);
                mma16(o_[nf], al, bh2);
                mma16(o_[nf], ah, bh2);
            }
        }
    }
    {
        int q0 = wq * 16 + g;
        float p0 = Ss[q0 * 260 + 256];
        float p1 = Ss[(q0 + 8) * 260 + 256];
        size_t vb = rowbase + (size_t)256 * 768 + hv;
        #pragma unroll
        for (int nf = 0; nf < 4; nf++) {
            int dw = wsub * 16 + nf * 4 + tig;
            uint32_t wh = qh[vb + dw], wl = ql[vb + dw];
            float v0 = bf_lo(wh) + bf_lo(wl);
            float v1 = bf_hi(wh) + bf_hi(wl);
            o_[nf][0] += p0 * v0; o_[nf][1] += p0 * v1;
            o_[nf][2] += p1 * v0; o_[nf][3] += p1 * v1;
        }
    }
    #pragma unroll
    for (int rh = 0; rh < 2; rh++) {
        int n = nbase + wq * 16 + g + rh * 8;
        if (n < NT) {
            #pragma unroll
            for (int nf = 0; nf < 4; nf++) {
                uint32_t hw_, lw_;
                bf16_split_pack(o_[nf][rh * 2], o_[nf][rh * 2 + 1], hw_, lw_);
                size_t off = (size_t)(b * NT + n) * 256 + h * 32 + wsub * 16 + nf * 4 + tig;
                oh[off] = hw_; ol[off] = lw_;
            }
        }
    }
}

// ============================================================
// cls row init
// ============================================================
__global__ void cls_kernel(const float* __restrict__ cls, const float* __restrict__ pos,
                           float* __restrict__ tok)
{
    int idx = blockIdx.x * blockDim.x + threadIdx.x;
    if (idx >= Bq * Dm) return;
    int d = idx & 511, b = idx >> 9;
    tok[(size_t)b * NT * Dm + d] = cls[d] + pos[d];
}

// ============================================================
// Head
// ============================================================
__global__ void head_kernel(const float* __restrict__ tok, const float* __restrict__ ng,
                            const float* __restrict__ nb, const float* __restrict__ hw,
                            const float* __restrict__ hb, float* __restrict__ out)
{
    int b = blockIdx.x, tid = threadIdx.x;
    __shared__ float red[128];
    const float* xr = tok + (size_t)b * NT * Dm;
    float v[4]; float s = 0.f;
    #pragma unroll
    for (int i = 0; i < 4; i++) { v[i] = xr[tid + 128 * i]; s += v[i]; }
    red[tid] = s; __syncthreads();
    for (int st = 64; st > 0; st >>= 1) { if (tid < st) red[tid] += red[tid + st]; __syncthreads(); }
    float mu = red[0] * (1.f / 512.f); __syncthreads();
    float s2 = 0.f;
    #pragma unroll
    for (int i = 0; i < 4; i++) { float dv = v[i] - mu; s2 += dv * dv; }
    red[tid] = s2; __syncthreads();
    for (int st = 64; st > 0; st >>= 1) { if (tid < st) red[tid] += red[tid + st]; __syncthreads(); }
    float inv = rsqrtf(red[0] * (1.f / 512.f) + 1e-5f);
    __syncthreads();

    float xn[4];
    #pragma unroll
    for (int i = 0; i < 4; i++) {
        int idx = tid + 128 * i;
        xn[i] = (v[i] - mu) * inv * ng[idx] + nb[idx];
    }

    for (int c = 0; c < 3; c++) {
        float p = 0.f;
        #pragma unroll
        for (int i = 0; i < 4; i++) {
            int idx = tid + 128 * i;
            p = fmaf(xn[i], hw[idx * 3 + c], p);
        }
        red[tid] = p; __syncthreads();
        for (int st = 64; st > 0; st >>= 1) { if (tid < st) red[tid] += red[tid + st]; __syncthreads(); }
        if (tid == 0) out[b * 3 + c] = red[0] + hb[c];
        __syncthreads();
    }
}

// ============================================================
// Launch
// ============================================================
static uint32_t* s_wTh = nullptr;
static uint32_t* s_wTl = nullptr;

static inline void launch_gemm(const uint32_t* Ah, const uint32_t* Al, size_t wOffW,
                               const float* bias, const float* res,
                               float* C, uint32_t* Ch, uint32_t* Cl,
                               const float* comb, const float* pos, float* tokout,
                               int M, int Nn, int K, int act)
{
    dim3 grid(Nn / 128, (M + 127) / 128);
    mma_gemm<<<grid, 256, GEMM_SMEM_BYTES>>>(Ah, Al, s_wTh + wOffW, s_wTl + wOffW,
                                             bias, res, C, Ch, Cl, comb, pos, tokout,
                                             M, Nn, K, act);
}

extern "C" void kernel_launch(void* const* d_in, const int* in_sizes, int n_in,
                              void* d_out, int out_size)
{
    const float* image   = (const float*)d_in[0];
    const float* ssw     = (const float*)d_in[1];
    const float* ssb     = (const float*)d_in[2];
    const float* ssg     = (const float*)d_in[3];
    const float* ssbeta  = (const float*)d_in[4];
    const float* sow     = (const float*)d_in[5];
    const float* sob     = (const float*)d_in[6];
    const float* sog     = (const float*)d_in[7];
    const float* sobeta  = (const float*)d_in[8];
    const float* fw      = (const float*)d_in[9];
    const float* fb      = (const float*)d_in[10];
    const float* cls     = (const float*)d_in[11];
    const float* pos     = (const float*)d_in[12];
    const float* ln1g    = (const float*)d_in[13];
    const float* ln1b    = (const float*)d_in[14];
    const float* qkvw    = (const float*)d_in[15];
    const float* qkvb    = (const float*)d_in[16];
    const float* projw   = (const float*)d_in[17];
    const float* projb   = (const float*)d_in[18];
    const float* temp    = (const float*)d_in[19];
    const float* ln2g    = (const float*)d_in[20];
    const float* ln2b    = (const float*)d_in[21];
    const float* w1      = (const float*)d_in[22];
    const float* b1      = (const float*)d_in[23];
    const float* w2      = (const float*)d_in[24];
    const float* b2      = (const float*)d_in[25];
    const float* ng      = (const float*)d_in[26];
    const float* nb      = (const float*)d_in[27];
    const float* hw      = (const float*)d_in[28];
    const float* hb      = (const float*)d_in[29];

    float *comb, *tok;
    uint32_t *combh, *combl, *xh, *xl, *qkvh, *qkvl, *oh, *ol, *hh, *hl;
    cudaGetSymbolAddress((void**)&comb,  g_comb);
    cudaGetSymbolAddress((void**)&tok,   g_tok);
    cudaGetSymbolAddress((void**)&combh, g_combh);
    cudaGetSymbolAddress((void**)&combl, g_combl);
    cudaGetSymbolAddress((void**)&xh,    g_xh);
    cudaGetSymbolAddress((void**)&xl,    g_xl);
    cudaGetSymbolAddress((void**)&qkvh,  g_qkvh);
    cudaGetSymbolAddress((void**)&qkvl,  g_qkvl);
    cudaGetSymbolAddress((void**)&oh,    g_oh);
    cudaGetSymbolAddress((void**)&ol,    g_ol);
    cudaGetSymbolAddress((void**)&hh,    g_hh);
    cudaGetSymbolAddress((void**)&hl,    g_hl);
    cudaGetSymbolAddress((void**)&s_wTh, g_wTh);
    cudaGetSymbolAddress((void**)&s_wTl, g_wTl);

    cudaFuncSetAttribute(mma_gemm, cudaFuncAttributeMaxDynamicSharedMemorySize, GEMM_SMEM_BYTES);
    cudaFuncSetAttribute(attn_kernel, cudaFuncAttributeMaxDynamicSharedMemorySize, ATTN_SMEM);

    const int Mtok = Bq * NT;   // 8224
    const int Mpat = Bq * NP;   // 8192

    cls_kernel<<<(Bq * Dm + 255) / 256, 256>>>(cls, pos, tok);
    transpose_all<<<25088, 256>>>(fw, qkvw, projw, w1, w2, s_wTh, s_wTl);
    spt_kernel<<<Mpat, 512>>>(image, ssw, ssb, ssg, ssbeta,
                              sow, sob, sog, sobeta, comb, combh, combl);
    // launch 3: gate GEMM (profiled slot)
    launch_gemm(combh, combl, FWT_OFFW, fb, nullptr, nullptr, nullptr, nullptr,
                comb, pos, tok, Mpat, Dm, 2 * Dm, /*gate-fuse*/3);

    for (int l = 0; l < NL; l++) {
        size_t lb = LAYER_OFFW(l);
        ln_kernel<<<Mtok, 128>>>(tok, ln1g + l * Dm, ln1b + l * Dm, xh, xl);
        launch_gemm(xh, xl, lb + QKVT_OFFW, qkvb + l * 3 * Dm, nullptr,
                    nullptr, qkvh, qkvl, nullptr, nullptr, nullptr, Mtok, 3 * Dm, Dm, 0);
        attn_kernel<<<dim3(QTILES, NH, Bq), 256, ATTN_SMEM>>>(qkvh, qkvl, temp + l * NH, oh, ol);
        launch_gemm(oh, ol, lb + PROJT_OFFW, projb + l * Dm, tok,
                    tok, nullptr, nullptr, nullptr, nullptr, nullptr, Mtok, Dm, Dm, 0);
        ln_kernel<<<Mtok, 128>>>(tok, ln2g + l * Dm, ln2b + l * Dm, xh, xl);
        launch_gemm(xh, xl, lb + W1T_OFFW, b1 + l * MLPD, nullptr,
                    nullptr, hh, hl, nullptr, nullptr, nullptr, Mtok, MLPD, Dm, /*gelu*/2);
        launch_gemm(hh, hl, lb + W2T_OFFW, b2 + l * Dm, tok,
                    tok, nullptr, nullptr, nullptr, nullptr, nullptr, Mtok, Dm, MLPD, 0);
    }

    head_kernel<<<Bq, 128>>>(tok, ng, nb, hw, hb, (float*)d_out);
}